// round 13
// baseline (speedup 1.0000x reference)
#include <cuda_runtime.h>
#include <cuda_fp16.h>
#include <cstdint>
#include <math.h>

#define BATCH 2
#define SEQ   2048
#define DMODEL 768
#define NHEADS 12
#define HDIM  64
#define MROWS (BATCH*SEQ)   // 4096
#define NELEM (MROWS*DMODEL)
#define WELEM (DMODEL*DMODEL)

// ---------------- scratch (device globals; allocation-free) ----------------
__device__ __half g_xh[NELEM],  g_xl[NELEM];
__device__ __half g_wth[4][WELEM], g_wtl[4][WELEM];   // transposed [n][k]
__device__ float  g_vraw[NELEM];
__device__ __half g_qh[NELEM], g_ql[NELEM];
__device__ __half g_kh[NELEM], g_kl[NELEM];
__device__ __half g_vth[NELEM], g_vtl[NELEM];          // [b][dglobal][t]
__device__ __half g_ath[NELEM], g_atl[NELEM];
__device__ float  g_cos[SEQ * (HDIM/2)];
__device__ float  g_sin[SEQ * (HDIM/2)];

// ---------------- fp16-split helpers ----------------
__device__ __forceinline__ void split_h(float x, __half& h, __half& l) {
    h = __float2half_rn(x);
    l = __float2half_rn(x - __half2float(h));
}
__device__ __forceinline__ unsigned pack2(__half a, __half b) {
    __half2 t = __halves2half2(a, b);
    return *(unsigned*)&t;
}
__device__ __forceinline__ void mma_f16(float* d, const unsigned* a, const unsigned* b, const float* c) {
    asm volatile(
        "mma.sync.aligned.m16n8k16.row.col.f32.f16.f16.f32 "
        "{%0,%1,%2,%3}, {%4,%5,%6,%7}, {%8,%9}, {%10,%11,%12,%13};\n"
        : "=f"(d[0]), "=f"(d[1]), "=f"(d[2]), "=f"(d[3])
        : "r"(a[0]), "r"(a[1]), "r"(a[2]), "r"(a[3]),
          "r"(b[0]), "r"(b[1]),
          "f"(c[0]), "f"(c[1]), "f"(c[2]), "f"(c[3]));
}
__device__ __forceinline__ void mma3h(float* d, const unsigned* ah, const unsigned* al,
                                      const unsigned* bh, const unsigned* bl) {
    mma_f16(d, al, bh, d);
    mma_f16(d, ah, bl, d);
    mma_f16(d, ah, bh, d);
}
__device__ __forceinline__ void ldsm_x4(unsigned* r, unsigned addr) {
    asm volatile("ldmatrix.sync.aligned.m8n8.x4.shared.b16 {%0,%1,%2,%3}, [%4];"
        : "=r"(r[0]), "=r"(r[1]), "=r"(r[2]), "=r"(r[3]) : "r"(addr));
}

__device__ __forceinline__ void cp_async16(void* smem, const void* gmem) {
    unsigned s = (unsigned)__cvta_generic_to_shared(smem);
    asm volatile("cp.async.cg.shared.global [%0], [%1], 16;\n" :: "r"(s), "l"(gmem));
}
__device__ __forceinline__ void cp_commit() { asm volatile("cp.async.commit_group;\n"); }
template<int N> __device__ __forceinline__ void cp_wait() {
    asm volatile("cp.async.wait_group %0;\n" :: "n"(N));
}

// ---------------- prepass: x split ----------------
__global__ void split_x_kernel(const float* __restrict__ src, __half* __restrict__ hi,
                               __half* __restrict__ lo, int n) {
    int i = blockIdx.x * blockDim.x + threadIdx.x;
    if (i >= n) return;
    split_h(src[i], hi[i], lo[i]);
}

// ---------------- prepass: weight transpose + split -> Wt[n][k] ----------------
__global__ void wtrans_kernel(const float* __restrict__ w0, const float* __restrict__ w1,
                              const float* __restrict__ w2, const float* __restrict__ w3,
                              __half* __restrict__ hi, __half* __restrict__ lo) {
    __shared__ float t[32][33];
    int w = blockIdx.z;
    const float* W = (w == 0) ? w0 : (w == 1) ? w1 : (w == 2) ? w2 : w3;
    int k0 = blockIdx.x * 32, n0 = blockIdx.y * 32;
    int tx = threadIdx.x, ty = threadIdx.y;
    t[ty][tx] = W[(size_t)(k0 + ty) * DMODEL + n0 + tx];
    __syncthreads();
    float v = t[tx][ty];
    size_t o = (size_t)w * WELEM + (size_t)(n0 + ty) * DMODEL + k0 + tx;
    split_h(v, hi[o], lo[o]);
}

// ---------------- prepass: V transpose + split -> vt[b][dglobal][t] ----------------
__global__ void vtrans_kernel(const float* __restrict__ vraw,
                              __half* __restrict__ hi, __half* __restrict__ lo) {
    __shared__ float t[32][33];
    int b = blockIdx.z;
    int t0 = blockIdx.x * 32, d0 = blockIdx.y * 32;
    int tx = threadIdx.x, ty = threadIdx.y;
    t[ty][tx] = vraw[(size_t)(b * SEQ + t0 + ty) * DMODEL + d0 + tx];
    __syncthreads();
    float v = t[tx][ty];
    size_t o = ((size_t)b * DMODEL + d0 + ty) * SEQ + t0 + tx;
    split_h(v, hi[o], lo[o]);
}

// ---------------- RoPE table ----------------
__global__ void rope_table_kernel(float* ct, float* st) {
    int idx = blockIdx.x * blockDim.x + threadIdx.x;
    if (idx >= SEQ * (HDIM/2)) return;
    int t = idx >> 5;
    int i = idx & 31;
    float inv_freq = powf(10000.0f, -(float)(2 * i) / (float)HDIM);
    float ang = (float)t * inv_freq;
    ct[idx] = cosf(ang);
    st[idx] = sinf(ang);
}

// ---------------- 3xFP16 GEMM (proven R7 mainloop: 80B stride, 2-stage) ----------------
// C[4096,768] = A[m][k] @ Bt[n][k]^T. 128x128 tile, BK=32, 256 threads, warp 32x64.
// mode 0 (QKV): z=0 -> rope+0.125+split -> qh/ql ; z=1 -> rope+split -> kh/kl ; z=2 -> vraw f32.
// mode 1 (Wo):  plain f32 store to Cplain.
#define GEMM_SMEM 81920   // halves: As_h[2][128][40]@0 | As_l@10240 | Bs_h@20480 | Bs_l@30720

__global__ __launch_bounds__(256, 2)
void gemm_f16_kernel(const __half* __restrict__ Ah, const __half* __restrict__ Al,
                     const __half* __restrict__ B0h, const __half* __restrict__ B0l,
                     const __half* __restrict__ B1h, const __half* __restrict__ B1l,
                     const __half* __restrict__ B2h, const __half* __restrict__ B2l,
                     const float* __restrict__ ct, const float* __restrict__ st,
                     __half* __restrict__ qh, __half* __restrict__ ql,
                     __half* __restrict__ kh, __half* __restrict__ kl,
                     float* __restrict__ vout, float* __restrict__ Cplain, int mode) {
    const int K = DMODEL;
    extern __shared__ __half smh[];

    int z = blockIdx.z;
    const __half* Bh = (z == 0) ? B0h : (z == 1) ? B1h : B2h;
    const __half* Bl = (z == 0) ? B0l : (z == 1) ? B1l : B2l;

    int tid  = threadIdx.x;
    int wid  = tid >> 5, lane = tid & 31;
    int g = lane >> 2, c = lane & 3;
    int wm = (wid & 3) * 32;
    int wn = (wid >> 2) * 64;
    int bm = blockIdx.y * 128, bn = blockIdx.x * 128;

    int lrow = tid >> 1, lseg = (tid & 1) * 16;

    // ldmatrix per-thread byte offsets (16B-aligned: stride 80B)
    unsigned smem_u = (unsigned)__cvta_generic_to_shared(smh);
    unsigned a_frag = smem_u + ((wm + (lane & 15)) * 40 + ((lane & 16) ? 8 : 0)) * 2;
    unsigned b_frag = smem_u + 40960 +
                      ((wn + (lane & 7) + ((lane & 16) ? 8 : 0)) * 40 + ((lane & 8) ? 8 : 0)) * 2;

    float acc[2][8][4];
#pragma unroll
    for (int mf = 0; mf < 2; mf++)
#pragma unroll
        for (int nf = 0; nf < 8; nf++)
#pragma unroll
            for (int j = 0; j < 4; j++) acc[mf][nf][j] = 0.0f;

    auto load_chunk = [&](int buf, int k0) {
        size_t ga = (size_t)(bm + lrow) * K + k0 + lseg;
        __half* da_h = smh + buf * 5120 + lrow * 40 + lseg;
        __half* da_l = da_h + 10240;
        cp_async16(da_h,     Ah + ga);
        cp_async16(da_h + 8, Ah + ga + 8);
        cp_async16(da_l,     Al + ga);
        cp_async16(da_l + 8, Al + ga + 8);
        size_t gb = (size_t)(bn + lrow) * K + k0 + lseg;
        __half* db_h = smh + 20480 + buf * 5120 + lrow * 40 + lseg;
        __half* db_l = db_h + 10240;
        cp_async16(db_h,     Bh + gb);
        cp_async16(db_h + 8, Bh + gb + 8);
        cp_async16(db_l,     Bl + gb);
        cp_async16(db_l + 8, Bl + gb + 8);
    };

    const int NCH = K / 32;  // 24
    load_chunk(0, 0); cp_commit();

    for (int ch = 0; ch < NCH; ch++) {
        int buf = ch & 1;
        if (ch + 1 < NCH) { load_chunk(buf ^ 1, (ch + 1) * 32); cp_commit(); cp_wait<1>(); }
        else              { cp_wait<0>(); }
        __syncthreads();

        unsigned abase = a_frag + buf * 10240;
        unsigned bbase = b_frag + buf * 10240;
#pragma unroll
        for (int ks = 0; ks < 2; ks++) {
            int kb = ks * 32;
            unsigned afh[2][4], afl[2][4], bfh[8][2], bfl[8][2];
            ldsm_x4(afh[0], abase + kb);
            ldsm_x4(afh[1], abase + 1280 + kb);
            ldsm_x4(afl[0], abase + 20480 + kb);
            ldsm_x4(afl[1], abase + 20480 + 1280 + kb);
#pragma unroll
            for (int p = 0; p < 4; p++) {
                unsigned r[4];
                ldsm_x4(r, bbase + p * 1280 + kb);
                bfh[2*p][0] = r[0]; bfh[2*p][1] = r[1]; bfh[2*p+1][0] = r[2]; bfh[2*p+1][1] = r[3];
                ldsm_x4(r, bbase + 20480 + p * 1280 + kb);
                bfl[2*p][0] = r[0]; bfl[2*p][1] = r[1]; bfl[2*p+1][0] = r[2]; bfl[2*p+1][1] = r[3];
            }
#pragma unroll
            for (int mf = 0; mf < 2; mf++)
#pragma unroll
                for (int nf = 0; nf < 8; nf++)
                    mma3h(acc[mf][nf], afh[mf], afl[mf], bfh[nf], bfl[nf]);
        }
        __syncthreads();
    }

    // ---------------- epilogue ----------------
    if (mode == 1) {
#pragma unroll
        for (int mf = 0; mf < 2; mf++) {
            int row0 = bm + wm + mf * 16 + g;
#pragma unroll
            for (int nf = 0; nf < 8; nf++) {
                int col = bn + wn + nf * 8 + 2 * c;
                *(float2*)(Cplain + (size_t)row0 * DMODEL + col)       = make_float2(acc[mf][nf][0], acc[mf][nf][1]);
                *(float2*)(Cplain + (size_t)(row0 + 8) * DMODEL + col) = make_float2(acc[mf][nf][2], acc[mf][nf][3]);
            }
        }
        return;
    }
    if (z == 2) {
#pragma unroll
        for (int mf = 0; mf < 2; mf++) {
            int row0 = bm + wm + mf * 16 + g;
#pragma unroll
            for (int nf = 0; nf < 8; nf++) {
                int col = bn + wn + nf * 8 + 2 * c;
                *(float2*)(vout + (size_t)row0 * DMODEL + col)       = make_float2(acc[mf][nf][0], acc[mf][nf][1]);
                *(float2*)(vout + (size_t)(row0 + 8) * DMODEL + col) = make_float2(acc[mf][nf][2], acc[mf][nf][3]);
            }
        }
        return;
    }
    // z==0 (q) or z==1 (k): rope + split in registers.
    // Warp n-range (64 cols) = one head; rope pairs col i (nf<4) with i+32 (nf+4).
    {
        bool isq = (z == 0);
        __half* oh_ = isq ? qh : kh;
        __half* ol_ = isq ? ql : kl;
        float scale = isq ? 0.125f : 1.0f;
#pragma unroll
        for (int mf = 0; mf < 2; mf++) {
#pragma unroll
            for (int rs = 0; rs < 2; rs++) {
                int row = bm + wm + mf * 16 + g + rs * 8;
                int t = row & (SEQ - 1);
#pragma unroll
                for (int nf = 0; nf < 4; nf++) {
                    int i0 = nf * 8 + 2 * c;              // head-local col (0..31)
                    float a0 = acc[mf][nf][rs * 2 + 0];
                    float a1 = acc[mf][nf][rs * 2 + 1];
                    float b0 = acc[mf][nf + 4][rs * 2 + 0];
                    float b1 = acc[mf][nf + 4][rs * 2 + 1];
                    float c0 = ct[t * 32 + i0],     s0 = st[t * 32 + i0];
                    float c1 = ct[t * 32 + i0 + 1], s1 = st[t * 32 + i0 + 1];
                    float rA0 = (a0 * c0 - b0 * s0) * scale;
                    float rB0 = (a0 * s0 + b0 * c0) * scale;
                    float rA1 = (a1 * c1 - b1 * s1) * scale;
                    float rB1 = (a1 * s1 + b1 * c1) * scale;
                    __half hA0, lA0, hA1, lA1, hB0, lB0, hB1, lB1;
                    split_h(rA0, hA0, lA0); split_h(rA1, hA1, lA1);
                    split_h(rB0, hB0, lB0); split_h(rB1, hB1, lB1);
                    size_t o = (size_t)row * DMODEL + bn + wn + i0;
                    *(unsigned*)&oh_[o]      = pack2(hA0, hA1);
                    *(unsigned*)&ol_[o]      = pack2(lA0, lA1);
                    *(unsigned*)&oh_[o + 32] = pack2(hB0, hB1);
                    *(unsigned*)&ol_[o + 32] = pack2(lB0, lB1);
                }
            }
        }
    }
}

// ---------------- 3xFP16 causal flash attention, 3-buffer single-barrier ----------------
#define HTSZ (64 * 72)                 // halves per tile (144B rows: 16B-aligned)
#define HTB  (HTSZ * 2)                // 9216 B
#define ATTN_SMEM (12 * HTB)           // 110592 B

__global__ __launch_bounds__(256, 2)
void attn_f16_kernel(const __half* __restrict__ qh, const __half* __restrict__ ql,
                     const __half* __restrict__ kh, const __half* __restrict__ kl,
                     const __half* __restrict__ vth, const __half* __restrict__ vtl,
                     __half* __restrict__ oh, __half* __restrict__ ol) {
    extern __shared__ __half sm[];
    // tiles: KH[3] | KL[3] | VH[3] | VL[3], each HTB bytes

    int qt = gridDim.x - 1 - blockIdx.x;   // heaviest blocks first
    int h = blockIdx.y, b = blockIdx.z;
    int tid = threadIdx.x;
    int warp = tid >> 5, lane = tid & 31;
    int g = lane >> 2, c = lane & 3;
    int qbase_w = qt * 128 + warp * 16;

    unsigned smem_u = (unsigned)__cvta_generic_to_shared(sm);
    unsigned kv_frag = smem_u + ((lane & 7) + ((lane & 16) ? 8 : 0)) * 144 + ((lane & 8) ? 16 : 0);

    unsigned qfh[4][4], qfl[4][4];
    {
        size_t b0 = (size_t)(b * SEQ + qbase_w + g)     * DMODEL + h * HDIM;
        size_t b1 = (size_t)(b * SEQ + qbase_w + g + 8) * DMODEL + h * HDIM;
#pragma unroll
        for (int ks = 0; ks < 4; ks++) {
            int k0 = ks * 16 + 2 * c;
            qfh[ks][0] = *(const unsigned*)&qh[b0 + k0];
            qfh[ks][1] = *(const unsigned*)&qh[b1 + k0];
            qfh[ks][2] = *(const unsigned*)&qh[b0 + k0 + 8];
            qfh[ks][3] = *(const unsigned*)&qh[b1 + k0 + 8];
            qfl[ks][0] = *(const unsigned*)&ql[b0 + k0];
            qfl[ks][1] = *(const unsigned*)&ql[b1 + k0];
            qfl[ks][2] = *(const unsigned*)&ql[b0 + k0 + 8];
            qfl[ks][3] = *(const unsigned*)&ql[b1 + k0 + 8];
        }
    }

    float oacc[8][4];
#pragma unroll
    for (int nf = 0; nf < 8; nf++)
#pragma unroll
        for (int j = 0; j < 4; j++) oacc[nf][j] = 0.0f;
    float m0 = -1e30f, m1 = -1e30f, l0 = 0.0f, l1 = 0.0f;
    int qr0 = qbase_w + g;
    int qr1 = qr0 + 8;

    auto load_kv = [&](int buf, int kt) {
        size_t kb_ = (size_t)(b * SEQ + kt * 64) * DMODEL + h * HDIM;
        size_t vb_ = ((size_t)b * DMODEL + h * HDIM) * SEQ + kt * 64;
        __half* dkh = sm + buf * HTSZ;
        __half* dkl = sm + (3 + buf) * HTSZ;
        __half* dvh = sm + (6 + buf) * HTSZ;
        __half* dvl = sm + (9 + buf) * HTSZ;
#pragma unroll
        for (int i = tid; i < 64 * 8; i += 256) {
            int row = i >> 3, seg = (i & 7) * 8;
            int so = row * 72 + seg;
            cp_async16(dkh + so, kh  + kb_ + (size_t)row * DMODEL + seg);
            cp_async16(dkl + so, kl  + kb_ + (size_t)row * DMODEL + seg);
            cp_async16(dvh + so, vth + vb_ + (size_t)row * SEQ    + seg);
            cp_async16(dvl + so, vtl + vb_ + (size_t)row * SEQ    + seg);
        }
    };

    const int kt_max = 2 * qt + 1;
    load_kv(0, 0); cp_commit();
    if (kt_max >= 1) { load_kv(1, 1); cp_commit(); }

    for (int kt = 0; kt <= kt_max; kt++) {
        int buf = kt % 3;
        if (kt < kt_max) cp_wait<1>(); else cp_wait<0>();
        __syncthreads();
        if (kt + 2 <= kt_max) { load_kv((kt + 2) % 3, kt + 2); cp_commit(); }

        int rel = qbase_w + 15 - kt * 64;
        int nblk = (rel < 0) ? 0 : min(8, (rel >> 3) + 1);
        int nblkS = (nblk + 1) & ~1;
        bool need_mask = (kt * 64 + 63 > qbase_w);

        if (nblkS > 0) {
            unsigned kh_b = kv_frag + buf * HTB;
            unsigned kl_b = kv_frag + (3 + buf) * HTB;

            float sc[8][4];
            int npair = nblkS >> 1;
            for (int p = 0; p < npair; p++) {
#pragma unroll
                for (int j = 0; j < 4; j++) { sc[2*p][j] = 0.0f; sc[2*p+1][j] = 0.0f; }
#pragma unroll
                for (int ks = 0; ks < 4; ks++) {
                    unsigned bh[4], bl[4];
                    ldsm_x4(bh, kh_b + p * 2304 + ks * 32);
                    ldsm_x4(bl, kl_b + p * 2304 + ks * 32);
                    mma3h(sc[2*p],   qfh[ks], qfl[ks], bh,     bl);
                    mma3h(sc[2*p+1], qfh[ks], qfl[ks], bh + 2, bl + 2);
                }
            }

            if (need_mask) {
                for (int nf = 0; nf < nblkS; nf++) {
#pragma unroll
                    for (int j = 0; j < 4; j++) {
                        int key = kt * 64 + nf * 8 + 2 * c + (j & 1);
                        int qr  = (j < 2) ? qr0 : qr1;
                        if (key > qr) sc[nf][j] = -1e30f;
                    }
                }
            }

            float mx0 = -1e30f, mx1 = -1e30f;
            for (int nf = 0; nf < nblkS; nf++) {
                mx0 = fmaxf(mx0, fmaxf(sc[nf][0], sc[nf][1]));
                mx1 = fmaxf(mx1, fmaxf(sc[nf][2], sc[nf][3]));
            }
            mx0 = fmaxf(mx0, __shfl_xor_sync(0xffffffffu, mx0, 1));
            mx0 = fmaxf(mx0, __shfl_xor_sync(0xffffffffu, mx0, 2));
            mx1 = fmaxf(mx1, __shfl_xor_sync(0xffffffffu, mx1, 1));
            mx1 = fmaxf(mx1, __shfl_xor_sync(0xffffffffu, mx1, 2));
            float nm0 = fmaxf(m0, mx0), nm1 = fmaxf(m1, mx1);
            float cor0 = __expf(m0 - nm0), cor1 = __expf(m1 - nm1);
            m0 = nm0; m1 = nm1;
            l0 *= cor0; l1 *= cor1;
#pragma unroll
            for (int nf = 0; nf < 8; nf++) {
                oacc[nf][0] *= cor0; oacc[nf][1] *= cor0;
                oacc[nf][2] *= cor1; oacc[nf][3] *= cor1;
            }
            for (int nf = 0; nf < nblkS; nf++) {
                sc[nf][0] = __expf(sc[nf][0] - m0);
                sc[nf][1] = __expf(sc[nf][1] - m0);
                sc[nf][2] = __expf(sc[nf][2] - m1);
                sc[nf][3] = __expf(sc[nf][3] - m1);
                l0 += sc[nf][0] + sc[nf][1];
                l1 += sc[nf][2] + sc[nf][3];
            }

            unsigned vh_b = kv_frag + (6 + buf) * HTB;
            unsigned vl_b = kv_frag + (9 + buf) * HTB;
            int nkb = nblkS >> 1;
            for (int kb = 0; kb < nkb; kb++) {
                __half h0, e0, h1, e1, h2, e2, h3, e3;
                unsigned ah[4], al[4];
                split_h(sc[2*kb][0], h0, e0);  split_h(sc[2*kb][1], h1, e1);
                ah[0] = pack2(h0, h1); al[0] = pack2(e0, e1);
                split_h(sc[2*kb][2], h2, e2);  split_h(sc[2*kb][3], h3, e3);
                ah[1] = pack2(h2, h3); al[1] = pack2(e2, e3);
                split_h(sc[2*kb+1][0], h0, e0); split_h(sc[2*kb+1][1], h1, e1);
                ah[2] = pack2(h0, h1); al[2] = pack2(e0, e1);
                split_h(sc[2*kb+1][2], h2, e2); split_h(sc[2*kb+1][3], h3, e3);
                ah[3] = pack2(h2, h3); al[3] = pack2(e2, e3);
#pragma unroll
                for (int p = 0; p < 4; p++) {
                    unsigned bh[4], bl[4];
                    ldsm_x4(bh, vh_b + p * 2304 + kb * 32);
                    ldsm_x4(bl, vl_b + p * 2304 + kb * 32);
                    mma3h(oacc[2*p],   ah, al, bh,     bl);
                    mma3h(oacc[2*p+1], ah, al, bh + 2, bl + 2);
                }
            }
        }
    }

    l0 += __shfl_xor_sync(0xffffffffu, l0, 1);
    l0 += __shfl_xor_sync(0xffffffffu, l0, 2);
    l1 += __shfl_xor_sync(0xffffffffu, l1, 1);
    l1 += __shfl_xor_sync(0xffffffffu, l1, 2);
    float inv0 = 1.0f / l0, inv1 = 1.0f / l1;

    size_t o0 = (size_t)(b * SEQ + qr0) * DMODEL + h * HDIM;
    size_t o1 = (size_t)(b * SEQ + qr1) * DMODEL + h * HDIM;
#pragma unroll
    for (int nf = 0; nf < 8; nf++) {
        int col = nf * 8 + 2 * c;
        split_h(oacc[nf][0] * inv0, oh[o0 + col],     ol[o0 + col]);
        split_h(oacc[nf][1] * inv0, oh[o0 + col + 1], ol[o0 + col + 1]);
        split_h(oacc[nf][2] * inv1, oh[o1 + col],     ol[o1 + col]);
        split_h(oacc[nf][3] * inv1, oh[o1 + col + 1], ol[o1 + col + 1]);
    }
}

// ---------------- launch ----------------
extern "C" void kernel_launch(void* const* d_in, const int* in_sizes, int n_in,
                              void* d_out, int out_size) {
    const float* x  = (const float*)d_in[0];
    const float* Wq = (const float*)d_in[1];
    const float* Wk = (const float*)d_in[2];
    const float* Wv = (const float*)d_in[3];
    const float* Wo = (const float*)d_in[4];
    float* out = (float*)d_out;

    cudaFuncSetAttribute(gemm_f16_kernel, cudaFuncAttributeMaxDynamicSharedMemorySize, GEMM_SMEM);
    cudaFuncSetAttribute(attn_f16_kernel, cudaFuncAttributeMaxDynamicSharedMemorySize, ATTN_SMEM);

    __half *xh, *xl, *wth, *wtl, *qh, *ql, *kh, *kl, *vth, *vtl, *ath, *atl;
    float *vraw, *ct, *st;
    cudaGetSymbolAddress((void**)&xh,   g_xh);
    cudaGetSymbolAddress((void**)&xl,   g_xl);
    cudaGetSymbolAddress((void**)&wth,  g_wth);
    cudaGetSymbolAddress((void**)&wtl,  g_wtl);
    cudaGetSymbolAddress((void**)&vraw, g_vraw);
    cudaGetSymbolAddress((void**)&qh,   g_qh);
    cudaGetSymbolAddress((void**)&ql,   g_ql);
    cudaGetSymbolAddress((void**)&kh,   g_kh);
    cudaGetSymbolAddress((void**)&kl,   g_kl);
    cudaGetSymbolAddress((void**)&vth,  g_vth);
    cudaGetSymbolAddress((void**)&vtl,  g_vtl);
    cudaGetSymbolAddress((void**)&ath,  g_ath);
    cudaGetSymbolAddress((void**)&atl,  g_atl);
    cudaGetSymbolAddress((void**)&ct,   g_cos);
    cudaGetSymbolAddress((void**)&st,   g_sin);

    {
        int n = SEQ * (HDIM/2);
        rope_table_kernel<<<(n + 255) / 256, 256>>>(ct, st);
    }

    split_x_kernel<<<(NELEM + 255) / 256, 256>>>(x, xh, xl, NELEM);
    wtrans_kernel<<<dim3(DMODEL/32, DMODEL/32, 4), dim3(32, 32)>>>(Wq, Wk, Wv, Wo, wth, wtl);

    // merged QKV projection with fused rope-split epilogue (z=0 q, z=1 k, z=2 v raw)
    dim3 qkv_grid(DMODEL / 128, MROWS / 128, 3);
    gemm_f16_kernel<<<qkv_grid, 256, GEMM_SMEM>>>(xh, xl,
                                    wth + 0 * WELEM, wtl + 0 * WELEM,
                                    wth + 1 * WELEM, wtl + 1 * WELEM,
                                    wth + 2 * WELEM, wtl + 2 * WELEM,
                                    ct, st, qh, ql, kh, kl, vraw, nullptr, 0);

    vtrans_kernel<<<dim3(SEQ/32, DMODEL/32, BATCH), dim3(32, 32)>>>(vraw, vth, vtl);

    attn_f16_kernel<<<dim3(SEQ / 128, NHEADS, BATCH), 256, ATTN_SMEM>>>(
        qh, ql, kh, kl, vth, vtl, ath, atl);

    // output projection (plain epilogue)
    dim3 o_grid(DMODEL / 128, MROWS / 128, 1);
    gemm_f16_kernel<<<o_grid, 256, GEMM_SMEM>>>(ath, atl,
                                  wth + 3 * WELEM, wtl + 3 * WELEM,
                                  wth + 3 * WELEM, wtl + 3 * WELEM,
                                  wth + 3 * WELEM, wtl + 3 * WELEM,
                                  ct, st, nullptr, nullptr, nullptr, nullptr, nullptr, out, 1);
}

// round 14
// speedup vs baseline: 1.1538x; 1.1538x over previous
#include <cuda_runtime.h>
#include <cuda_fp16.h>
#include <cstdint>
#include <math.h>

#define BATCH 2
#define SEQ   2048
#define DMODEL 768
#define NHEADS 12
#define HDIM  64
#define MROWS (BATCH*SEQ)   // 4096
#define NELEM (MROWS*DMODEL)
#define WELEM (DMODEL*DMODEL)

// ---------------- scratch (device globals; allocation-free) ----------------
__device__ __half g_xh[NELEM],  g_xl[NELEM];
__device__ __half g_wth[4][WELEM], g_wtl[4][WELEM];   // transposed [n][k]
__device__ float  g_vraw[NELEM];
__device__ __half g_qh[NELEM], g_ql[NELEM];
__device__ __half g_kh[NELEM], g_kl[NELEM];
__device__ __half g_vth[NELEM], g_vtl[NELEM];          // [b][dglobal][t]
__device__ __half g_ath[NELEM];                        // attention out (fp16 only)
__device__ float  g_cos[SEQ * (HDIM/2)];
__device__ float  g_sin[SEQ * (HDIM/2)];

// ---------------- fp16-split helpers ----------------
__device__ __forceinline__ void split_h(float x, __half& h, __half& l) {
    h = __float2half_rn(x);
    l = __float2half_rn(x - __half2float(h));
}
__device__ __forceinline__ unsigned pack2(__half a, __half b) {
    __half2 t = __halves2half2(a, b);
    return *(unsigned*)&t;
}
__device__ __forceinline__ void mma_f16(float* d, const unsigned* a, const unsigned* b, const float* c) {
    asm volatile(
        "mma.sync.aligned.m16n8k16.row.col.f32.f16.f16.f32 "
        "{%0,%1,%2,%3}, {%4,%5,%6,%7}, {%8,%9}, {%10,%11,%12,%13};\n"
        : "=f"(d[0]), "=f"(d[1]), "=f"(d[2]), "=f"(d[3])
        : "r"(a[0]), "r"(a[1]), "r"(a[2]), "r"(a[3]),
          "r"(b[0]), "r"(b[1]),
          "f"(c[0]), "f"(c[1]), "f"(c[2]), "f"(c[3]));
}
__device__ __forceinline__ void mma3h(float* d, const unsigned* ah, const unsigned* al,
                                      const unsigned* bh, const unsigned* bl) {
    mma_f16(d, al, bh, d);
    mma_f16(d, ah, bl, d);
    mma_f16(d, ah, bh, d);
}
__device__ __forceinline__ void ldsm_x4(unsigned* r, unsigned addr) {
    asm volatile("ldmatrix.sync.aligned.m8n8.x4.shared.b16 {%0,%1,%2,%3}, [%4];"
        : "=r"(r[0]), "=r"(r[1]), "=r"(r[2]), "=r"(r[3]) : "r"(addr));
}

__device__ __forceinline__ void cp_async16(void* smem, const void* gmem) {
    unsigned s = (unsigned)__cvta_generic_to_shared(smem);
    asm volatile("cp.async.cg.shared.global [%0], [%1], 16;\n" :: "r"(s), "l"(gmem));
}
__device__ __forceinline__ void cp_commit() { asm volatile("cp.async.commit_group;\n"); }
template<int N> __device__ __forceinline__ void cp_wait() {
    asm volatile("cp.async.wait_group %0;\n" :: "n"(N));
}

// ---------------- prepass: x split ----------------
__global__ void split_x_kernel(const float* __restrict__ src, __half* __restrict__ hi,
                               __half* __restrict__ lo, int n) {
    int i = blockIdx.x * blockDim.x + threadIdx.x;
    if (i >= n) return;
    split_h(src[i], hi[i], lo[i]);
}

// ---------------- prepass: weight transpose + split -> Wt[n][k] ----------------
__global__ void wtrans_kernel(const float* __restrict__ w0, const float* __restrict__ w1,
                              const float* __restrict__ w2, const float* __restrict__ w3,
                              __half* __restrict__ hi, __half* __restrict__ lo) {
    __shared__ float t[32][33];
    int w = blockIdx.z;
    const float* W = (w == 0) ? w0 : (w == 1) ? w1 : (w == 2) ? w2 : w3;
    int k0 = blockIdx.x * 32, n0 = blockIdx.y * 32;
    int tx = threadIdx.x, ty = threadIdx.y;
    t[ty][tx] = W[(size_t)(k0 + ty) * DMODEL + n0 + tx];
    __syncthreads();
    float v = t[tx][ty];
    size_t o = (size_t)w * WELEM + (size_t)(n0 + ty) * DMODEL + k0 + tx;
    split_h(v, hi[o], lo[o]);
}

// ---------------- prepass: V transpose + split -> vt[b][dglobal][t] ----------------
__global__ void vtrans_kernel(const float* __restrict__ vraw,
                              __half* __restrict__ hi, __half* __restrict__ lo) {
    __shared__ float t[32][33];
    int b = blockIdx.z;
    int t0 = blockIdx.x * 32, d0 = blockIdx.y * 32;
    int tx = threadIdx.x, ty = threadIdx.y;
    t[ty][tx] = vraw[(size_t)(b * SEQ + t0 + ty) * DMODEL + d0 + tx];
    __syncthreads();
    float v = t[tx][ty];
    size_t o = ((size_t)b * DMODEL + d0 + ty) * SEQ + t0 + tx;
    split_h(v, hi[o], lo[o]);
}

// ---------------- RoPE table ----------------
__global__ void rope_table_kernel(float* ct, float* st) {
    int idx = blockIdx.x * blockDim.x + threadIdx.x;
    if (idx >= SEQ * (HDIM/2)) return;
    int t = idx >> 5;
    int i = idx & 31;
    float inv_freq = powf(10000.0f, -(float)(2 * i) / (float)HDIM);
    float ang = (float)t * inv_freq;
    ct[idx] = cosf(ang);
    st[idx] = sinf(ang);
}

// ---------------- FP16-emulated GEMM (80B stride, 2-stage) ----------------
// C[4096,768] = A[m][k] @ Bt[n][k]^T. 128x128 tile, BK=32, 256 threads, warp 32x64.
// mode 0 (QKV, 3-term): z=0 -> rope+0.125+split -> qh/ql ; z=1 -> rope+split; z=2 -> vraw f32.
// mode 1 (Wo, 2-term: Ah*(Bh+Bl)):  plain f32 store to Cplain.
#define GEMM_SMEM 81920   // halves: As_h[2][128][40]@0 | As_l@10240 | Bs_h@20480 | Bs_l@30720

__global__ __launch_bounds__(256, 2)
void gemm_f16_kernel(const __half* __restrict__ Ah, const __half* __restrict__ Al,
                     const __half* __restrict__ B0h, const __half* __restrict__ B0l,
                     const __half* __restrict__ B1h, const __half* __restrict__ B1l,
                     const __half* __restrict__ B2h, const __half* __restrict__ B2l,
                     const float* __restrict__ ct, const float* __restrict__ st,
                     __half* __restrict__ qh, __half* __restrict__ ql,
                     __half* __restrict__ kh, __half* __restrict__ kl,
                     float* __restrict__ vout, float* __restrict__ Cplain, int mode) {
    const int K = DMODEL;
    extern __shared__ __half smh[];

    int z = blockIdx.z;
    const __half* Bh = (z == 0) ? B0h : (z == 1) ? B1h : B2h;
    const __half* Bl = (z == 0) ? B0l : (z == 1) ? B1l : B2l;

    int tid  = threadIdx.x;
    int wid  = tid >> 5, lane = tid & 31;
    int g = lane >> 2, c = lane & 3;
    int wm = (wid & 3) * 32;
    int wn = (wid >> 2) * 64;
    int bm = blockIdx.y * 128, bn = blockIdx.x * 128;

    int lrow = tid >> 1, lseg = (tid & 1) * 16;

    unsigned smem_u = (unsigned)__cvta_generic_to_shared(smh);
    unsigned a_frag = smem_u + ((wm + (lane & 15)) * 40 + ((lane & 16) ? 8 : 0)) * 2;
    unsigned b_frag = smem_u + 40960 +
                      ((wn + (lane & 7) + ((lane & 16) ? 8 : 0)) * 40 + ((lane & 8) ? 8 : 0)) * 2;

    float acc[2][8][4];
#pragma unroll
    for (int mf = 0; mf < 2; mf++)
#pragma unroll
        for (int nf = 0; nf < 8; nf++)
#pragma unroll
            for (int j = 0; j < 4; j++) acc[mf][nf][j] = 0.0f;

    auto load_chunk = [&](int buf, int k0) {
        size_t ga = (size_t)(bm + lrow) * K + k0 + lseg;
        __half* da_h = smh + buf * 5120 + lrow * 40 + lseg;
        cp_async16(da_h,     Ah + ga);
        cp_async16(da_h + 8, Ah + ga + 8);
        if (mode == 0) {
            __half* da_l = da_h + 10240;
            cp_async16(da_l,     Al + ga);
            cp_async16(da_l + 8, Al + ga + 8);
        }
        size_t gb = (size_t)(bn + lrow) * K + k0 + lseg;
        __half* db_h = smh + 20480 + buf * 5120 + lrow * 40 + lseg;
        __half* db_l = db_h + 10240;
        cp_async16(db_h,     Bh + gb);
        cp_async16(db_h + 8, Bh + gb + 8);
        cp_async16(db_l,     Bl + gb);
        cp_async16(db_l + 8, Bl + gb + 8);
    };

    const int NCH = K / 32;  // 24
    load_chunk(0, 0); cp_commit();

    for (int ch = 0; ch < NCH; ch++) {
        int buf = ch & 1;
        if (ch + 1 < NCH) { load_chunk(buf ^ 1, (ch + 1) * 32); cp_commit(); cp_wait<1>(); }
        else              { cp_wait<0>(); }
        __syncthreads();

        unsigned abase = a_frag + buf * 10240;
        unsigned bbase = b_frag + buf * 10240;
#pragma unroll
        for (int ks = 0; ks < 2; ks++) {
            int kb = ks * 32;
            unsigned afh[2][4], afl[2][4], bfh[8][2], bfl[8][2];
            ldsm_x4(afh[0], abase + kb);
            ldsm_x4(afh[1], abase + 1280 + kb);
            if (mode == 0) {
                ldsm_x4(afl[0], abase + 20480 + kb);
                ldsm_x4(afl[1], abase + 20480 + 1280 + kb);
            }
#pragma unroll
            for (int p = 0; p < 4; p++) {
                unsigned r[4];
                ldsm_x4(r, bbase + p * 1280 + kb);
                bfh[2*p][0] = r[0]; bfh[2*p][1] = r[1]; bfh[2*p+1][0] = r[2]; bfh[2*p+1][1] = r[3];
                ldsm_x4(r, bbase + 20480 + p * 1280 + kb);
                bfl[2*p][0] = r[0]; bfl[2*p][1] = r[1]; bfl[2*p+1][0] = r[2]; bfl[2*p+1][1] = r[3];
            }
#pragma unroll
            for (int mf = 0; mf < 2; mf++)
#pragma unroll
                for (int nf = 0; nf < 8; nf++) {
                    if (mode == 0) mma_f16(acc[mf][nf], afl[mf], bfh[nf], acc[mf][nf]);
                    mma_f16(acc[mf][nf], afh[mf], bfl[nf], acc[mf][nf]);
                    mma_f16(acc[mf][nf], afh[mf], bfh[nf], acc[mf][nf]);
                }
        }
        __syncthreads();
    }

    // ---------------- epilogue ----------------
    if (mode == 1) {
#pragma unroll
        for (int mf = 0; mf < 2; mf++) {
            int row0 = bm + wm + mf * 16 + g;
#pragma unroll
            for (int nf = 0; nf < 8; nf++) {
                int col = bn + wn + nf * 8 + 2 * c;
                *(float2*)(Cplain + (size_t)row0 * DMODEL + col)       = make_float2(acc[mf][nf][0], acc[mf][nf][1]);
                *(float2*)(Cplain + (size_t)(row0 + 8) * DMODEL + col) = make_float2(acc[mf][nf][2], acc[mf][nf][3]);
            }
        }
        return;
    }
    if (z == 2) {
#pragma unroll
        for (int mf = 0; mf < 2; mf++) {
            int row0 = bm + wm + mf * 16 + g;
#pragma unroll
            for (int nf = 0; nf < 8; nf++) {
                int col = bn + wn + nf * 8 + 2 * c;
                *(float2*)(vout + (size_t)row0 * DMODEL + col)       = make_float2(acc[mf][nf][0], acc[mf][nf][1]);
                *(float2*)(vout + (size_t)(row0 + 8) * DMODEL + col) = make_float2(acc[mf][nf][2], acc[mf][nf][3]);
            }
        }
        return;
    }
    // z==0 (q) or z==1 (k): rope + split in registers (warp n-range = one head)
    {
        bool isq = (z == 0);
        __half* oh_ = isq ? qh : kh;
        __half* ol_ = isq ? ql : kl;
        float scale = isq ? 0.125f : 1.0f;
#pragma unroll
        for (int mf = 0; mf < 2; mf++) {
#pragma unroll
            for (int rs = 0; rs < 2; rs++) {
                int row = bm + wm + mf * 16 + g + rs * 8;
                int t = row & (SEQ - 1);
#pragma unroll
                for (int nf = 0; nf < 4; nf++) {
                    int i0 = nf * 8 + 2 * c;
                    float a0 = acc[mf][nf][rs * 2 + 0];
                    float a1 = acc[mf][nf][rs * 2 + 1];
                    float b0 = acc[mf][nf + 4][rs * 2 + 0];
                    float b1 = acc[mf][nf + 4][rs * 2 + 1];
                    float c0 = ct[t * 32 + i0],     s0 = st[t * 32 + i0];
                    float c1 = ct[t * 32 + i0 + 1], s1 = st[t * 32 + i0 + 1];
                    float rA0 = (a0 * c0 - b0 * s0) * scale;
                    float rB0 = (a0 * s0 + b0 * c0) * scale;
                    float rA1 = (a1 * c1 - b1 * s1) * scale;
                    float rB1 = (a1 * s1 + b1 * c1) * scale;
                    __half hA0, lA0, hA1, lA1, hB0, lB0, hB1, lB1;
                    split_h(rA0, hA0, lA0); split_h(rA1, hA1, lA1);
                    split_h(rB0, hB0, lB0); split_h(rB1, hB1, lB1);
                    size_t o = (size_t)row * DMODEL + bn + wn + i0;
                    *(unsigned*)&oh_[o]      = pack2(hA0, hA1);
                    *(unsigned*)&ol_[o]      = pack2(lA0, lA1);
                    *(unsigned*)&oh_[o + 32] = pack2(hB0, hB1);
                    *(unsigned*)&ol_[o + 32] = pack2(lB0, lB1);
                }
            }
        }
    }
}

// ---------------- causal flash attention: 3-term S, 2-term PV ----------------
#define HTSZ (64 * 72)                 // halves per tile (144B rows, 16B-aligned)
#define HTB  (HTSZ * 2)                // 9216 B
#define ATTN_SMEM (12 * HTB)           // 110592 B

__global__ __launch_bounds__(256, 2)
void attn_f16_kernel(const __half* __restrict__ qh, const __half* __restrict__ ql,
                     const __half* __restrict__ kh, const __half* __restrict__ kl,
                     const __half* __restrict__ vth, const __half* __restrict__ vtl,
                     __half* __restrict__ oh) {
    extern __shared__ __half sm[];
    // tiles: KH[3] | KL[3] | VH[3] | VL[3], each HTB bytes

    int qt = gridDim.x - 1 - blockIdx.x;   // heaviest blocks first
    int h = blockIdx.y, b = blockIdx.z;
    int tid = threadIdx.x;
    int warp = tid >> 5, lane = tid & 31;
    int g = lane >> 2, c = lane & 3;
    int qbase_w = qt * 128 + warp * 16;

    unsigned smem_u = (unsigned)__cvta_generic_to_shared(sm);
    unsigned kv_frag = smem_u + ((lane & 7) + ((lane & 16) ? 8 : 0)) * 144 + ((lane & 8) ? 16 : 0);

    unsigned qfh[4][4], qfl[4][4];
    {
        size_t b0 = (size_t)(b * SEQ + qbase_w + g)     * DMODEL + h * HDIM;
        size_t b1 = (size_t)(b * SEQ + qbase_w + g + 8) * DMODEL + h * HDIM;
#pragma unroll
        for (int ks = 0; ks < 4; ks++) {
            int k0 = ks * 16 + 2 * c;
            qfh[ks][0] = *(const unsigned*)&qh[b0 + k0];
            qfh[ks][1] = *(const unsigned*)&qh[b1 + k0];
            qfh[ks][2] = *(const unsigned*)&qh[b0 + k0 + 8];
            qfh[ks][3] = *(const unsigned*)&qh[b1 + k0 + 8];
            qfl[ks][0] = *(const unsigned*)&ql[b0 + k0];
            qfl[ks][1] = *(const unsigned*)&ql[b1 + k0];
            qfl[ks][2] = *(const unsigned*)&ql[b0 + k0 + 8];
            qfl[ks][3] = *(const unsigned*)&ql[b1 + k0 + 8];
        }
    }

    float oacc[8][4];
#pragma unroll
    for (int nf = 0; nf < 8; nf++)
#pragma unroll
        for (int j = 0; j < 4; j++) oacc[nf][j] = 0.0f;
    float m0 = -1e30f, m1 = -1e30f, l0 = 0.0f, l1 = 0.0f;
    int qr0 = qbase_w + g;
    int qr1 = qr0 + 8;

    auto load_kv = [&](int buf, int kt) {
        size_t kb_ = (size_t)(b * SEQ + kt * 64) * DMODEL + h * HDIM;
        size_t vb_ = ((size_t)b * DMODEL + h * HDIM) * SEQ + kt * 64;
        __half* dkh = sm + buf * HTSZ;
        __half* dkl = sm + (3 + buf) * HTSZ;
        __half* dvh = sm + (6 + buf) * HTSZ;
        __half* dvl = sm + (9 + buf) * HTSZ;
#pragma unroll
        for (int i = tid; i < 64 * 8; i += 256) {
            int row = i >> 3, seg = (i & 7) * 8;
            int so = row * 72 + seg;
            cp_async16(dkh + so, kh  + kb_ + (size_t)row * DMODEL + seg);
            cp_async16(dkl + so, kl  + kb_ + (size_t)row * DMODEL + seg);
            cp_async16(dvh + so, vth + vb_ + (size_t)row * SEQ    + seg);
            cp_async16(dvl + so, vtl + vb_ + (size_t)row * SEQ    + seg);
        }
    };

    const int kt_max = 2 * qt + 1;
    load_kv(0, 0); cp_commit();
    if (kt_max >= 1) { load_kv(1, 1); cp_commit(); }

    for (int kt = 0; kt <= kt_max; kt++) {
        int buf = kt % 3;
        if (kt < kt_max) cp_wait<1>(); else cp_wait<0>();
        __syncthreads();
        if (kt + 2 <= kt_max) { load_kv((kt + 2) % 3, kt + 2); cp_commit(); }

        int rel = qbase_w + 15 - kt * 64;
        int nblk = (rel < 0) ? 0 : min(8, (rel >> 3) + 1);
        int nblkS = (nblk + 1) & ~1;
        bool need_mask = (kt * 64 + 63 > qbase_w);

        if (nblkS > 0) {
            unsigned kh_b = kv_frag + buf * HTB;
            unsigned kl_b = kv_frag + (3 + buf) * HTB;

            // S = Q K^T (3-term, full 22-bit)
            float sc[8][4];
            int npair = nblkS >> 1;
            for (int p = 0; p < npair; p++) {
#pragma unroll
                for (int j = 0; j < 4; j++) { sc[2*p][j] = 0.0f; sc[2*p+1][j] = 0.0f; }
#pragma unroll
                for (int ks = 0; ks < 4; ks++) {
                    unsigned bh[4], bl[4];
                    ldsm_x4(bh, kh_b + p * 2304 + ks * 32);
                    ldsm_x4(bl, kl_b + p * 2304 + ks * 32);
                    mma3h(sc[2*p],   qfh[ks], qfl[ks], bh,     bl);
                    mma3h(sc[2*p+1], qfh[ks], qfl[ks], bh + 2, bl + 2);
                }
            }

            if (need_mask) {
                for (int nf = 0; nf < nblkS; nf++) {
#pragma unroll
                    for (int j = 0; j < 4; j++) {
                        int key = kt * 64 + nf * 8 + 2 * c + (j & 1);
                        int qr  = (j < 2) ? qr0 : qr1;
                        if (key > qr) sc[nf][j] = -1e30f;
                    }
                }
            }

            float mx0 = -1e30f, mx1 = -1e30f;
            for (int nf = 0; nf < nblkS; nf++) {
                mx0 = fmaxf(mx0, fmaxf(sc[nf][0], sc[nf][1]));
                mx1 = fmaxf(mx1, fmaxf(sc[nf][2], sc[nf][3]));
            }
            mx0 = fmaxf(mx0, __shfl_xor_sync(0xffffffffu, mx0, 1));
            mx0 = fmaxf(mx0, __shfl_xor_sync(0xffffffffu, mx0, 2));
            mx1 = fmaxf(mx1, __shfl_xor_sync(0xffffffffu, mx1, 1));
            mx1 = fmaxf(mx1, __shfl_xor_sync(0xffffffffu, mx1, 2));
            float nm0 = fmaxf(m0, mx0), nm1 = fmaxf(m1, mx1);
            float cor0 = __expf(m0 - nm0), cor1 = __expf(m1 - nm1);
            m0 = nm0; m1 = nm1;
            l0 *= cor0; l1 *= cor1;
#pragma unroll
            for (int nf = 0; nf < 8; nf++) {
                oacc[nf][0] *= cor0; oacc[nf][1] *= cor0;
                oacc[nf][2] *= cor1; oacc[nf][3] *= cor1;
            }
            for (int nf = 0; nf < nblkS; nf++) {
                sc[nf][0] = __expf(sc[nf][0] - m0);
                sc[nf][1] = __expf(sc[nf][1] - m0);
                sc[nf][2] = __expf(sc[nf][2] - m1);
                sc[nf][3] = __expf(sc[nf][3] - m1);
                l0 += sc[nf][0] + sc[nf][1];
                l1 += sc[nf][2] + sc[nf][3];
            }

            // O += P V  (2-term: P fp16 single, V 22-bit; no P splits)
            unsigned vh_b = kv_frag + (6 + buf) * HTB;
            unsigned vl_b = kv_frag + (9 + buf) * HTB;
            int nkb = nblkS >> 1;
            for (int kb = 0; kb < nkb; kb++) {
                unsigned ah[4];
                ah[0] = pack2(__float2half_rn(sc[2*kb][0]),   __float2half_rn(sc[2*kb][1]));
                ah[1] = pack2(__float2half_rn(sc[2*kb][2]),   __float2half_rn(sc[2*kb][3]));
                ah[2] = pack2(__float2half_rn(sc[2*kb+1][0]), __float2half_rn(sc[2*kb+1][1]));
                ah[3] = pack2(__float2half_rn(sc[2*kb+1][2]), __float2half_rn(sc[2*kb+1][3]));
#pragma unroll
                for (int p = 0; p < 4; p++) {
                    unsigned bh[4], bl[4];
                    ldsm_x4(bh, vh_b + p * 2304 + kb * 32);
                    ldsm_x4(bl, vl_b + p * 2304 + kb * 32);
                    mma_f16(oacc[2*p],   ah, bl,     oacc[2*p]);
                    mma_f16(oacc[2*p],   ah, bh,     oacc[2*p]);
                    mma_f16(oacc[2*p+1], ah, bl + 2, oacc[2*p+1]);
                    mma_f16(oacc[2*p+1], ah, bh + 2, oacc[2*p+1]);
                }
            }
        }
    }

    l0 += __shfl_xor_sync(0xffffffffu, l0, 1);
    l0 += __shfl_xor_sync(0xffffffffu, l0, 2);
    l1 += __shfl_xor_sync(0xffffffffu, l1, 1);
    l1 += __shfl_xor_sync(0xffffffffu, l1, 2);
    float inv0 = 1.0f / l0, inv1 = 1.0f / l1;

    // store fp16-only (Wo GEMM consumes 2-term: Ah * (Bh+Bl))
    size_t o0 = (size_t)(b * SEQ + qr0) * DMODEL + h * HDIM;
    size_t o1 = (size_t)(b * SEQ + qr1) * DMODEL + h * HDIM;
#pragma unroll
    for (int nf = 0; nf < 8; nf++) {
        int col = nf * 8 + 2 * c;
        *(unsigned*)&oh[o0 + col] = pack2(__float2half_rn(oacc[nf][0] * inv0),
                                          __float2half_rn(oacc[nf][1] * inv0));
        *(unsigned*)&oh[o1 + col] = pack2(__float2half_rn(oacc[nf][2] * inv1),
                                          __float2half_rn(oacc[nf][3] * inv1));
    }
}

// ---------------- launch ----------------
extern "C" void kernel_launch(void* const* d_in, const int* in_sizes, int n_in,
                              void* d_out, int out_size) {
    const float* x  = (const float*)d_in[0];
    const float* Wq = (const float*)d_in[1];
    const float* Wk = (const float*)d_in[2];
    const float* Wv = (const float*)d_in[3];
    const float* Wo = (const float*)d_in[4];
    float* out = (float*)d_out;

    cudaFuncSetAttribute(gemm_f16_kernel, cudaFuncAttributeMaxDynamicSharedMemorySize, GEMM_SMEM);
    cudaFuncSetAttribute(attn_f16_kernel, cudaFuncAttributeMaxDynamicSharedMemorySize, ATTN_SMEM);

    __half *xh, *xl, *wth, *wtl, *qh, *ql, *kh, *kl, *vth, *vtl, *ath;
    float *vraw, *ct, *st;
    cudaGetSymbolAddress((void**)&xh,   g_xh);
    cudaGetSymbolAddress((void**)&xl,   g_xl);
    cudaGetSymbolAddress((void**)&wth,  g_wth);
    cudaGetSymbolAddress((void**)&wtl,  g_wtl);
    cudaGetSymbolAddress((void**)&vraw, g_vraw);
    cudaGetSymbolAddress((void**)&qh,   g_qh);
    cudaGetSymbolAddress((void**)&ql,   g_ql);
    cudaGetSymbolAddress((void**)&kh,   g_kh);
    cudaGetSymbolAddress((void**)&kl,   g_kl);
    cudaGetSymbolAddress((void**)&vth,  g_vth);
    cudaGetSymbolAddress((void**)&vtl,  g_vtl);
    cudaGetSymbolAddress((void**)&ath,  g_ath);
    cudaGetSymbolAddress((void**)&ct,   g_cos);
    cudaGetSymbolAddress((void**)&st,   g_sin);

    {
        int n = SEQ * (HDIM/2);
        rope_table_kernel<<<(n + 255) / 256, 256>>>(ct, st);
    }

    split_x_kernel<<<(NELEM + 255) / 256, 256>>>(x, xh, xl, NELEM);
    wtrans_kernel<<<dim3(DMODEL/32, DMODEL/32, 4), dim3(32, 32)>>>(Wq, Wk, Wv, Wo, wth, wtl);

    // merged QKV projection with fused rope-split epilogue (3-term)
    dim3 qkv_grid(DMODEL / 128, MROWS / 128, 3);
    gemm_f16_kernel<<<qkv_grid, 256, GEMM_SMEM>>>(xh, xl,
                                    wth + 0 * WELEM, wtl + 0 * WELEM,
                                    wth + 1 * WELEM, wtl + 1 * WELEM,
                                    wth + 2 * WELEM, wtl + 2 * WELEM,
                                    ct, st, qh, ql, kh, kl, vraw, nullptr, 0);

    vtrans_kernel<<<dim3(SEQ/32, DMODEL/32, BATCH), dim3(32, 32)>>>(vraw, vth, vtl);

    attn_f16_kernel<<<dim3(SEQ / 128, NHEADS, BATCH), 256, ATTN_SMEM>>>(
        qh, ql, kh, kl, vth, vtl, ath);

    // output projection (2-term: Ah*(Bh+Bl); Al unused -> pass ath)
    dim3 o_grid(DMODEL / 128, MROWS / 128, 1);
    gemm_f16_kernel<<<o_grid, 256, GEMM_SMEM>>>(ath, ath,
                                  wth + 3 * WELEM, wtl + 3 * WELEM,
                                  wth + 3 * WELEM, wtl + 3 * WELEM,
                                  wth + 3 * WELEM, wtl + 3 * WELEM,
                                  ct, st, nullptr, nullptr, nullptr, nullptr, nullptr, out, 1);
}

// round 15
// speedup vs baseline: 1.2440x; 1.0782x over previous
#include <cuda_runtime.h>
#include <cuda_fp16.h>
#include <cstdint>
#include <math.h>

#define BATCH 2
#define SEQ   2048
#define DMODEL 768
#define NHEADS 12
#define HDIM  64
#define MROWS (BATCH*SEQ)   // 4096
#define NELEM (MROWS*DMODEL)
#define WELEM (DMODEL*DMODEL)

// ---------------- scratch (device globals; allocation-free) ----------------
__device__ __half g_xh[NELEM],  g_xl[NELEM];
__device__ __half g_wth[4][WELEM], g_wtl[4][WELEM];   // transposed [n][k]
__device__ float  g_vraw[NELEM];
__device__ __half g_qh[NELEM], g_ql[NELEM];
__device__ __half g_kh[NELEM];                         // K fp16-only
__device__ __half g_vth[NELEM], g_vtl[NELEM];          // [b][dglobal][t]
__device__ __half g_ath[NELEM];                        // attention out (fp16 only)
__device__ float  g_cos[SEQ * (HDIM/2)];
__device__ float  g_sin[SEQ * (HDIM/2)];

// ---------------- fp16-split helpers ----------------
__device__ __forceinline__ void split_h(float x, __half& h, __half& l) {
    h = __float2half_rn(x);
    l = __float2half_rn(x - __half2float(h));
}
__device__ __forceinline__ unsigned pack2(__half a, __half b) {
    __half2 t = __halves2half2(a, b);
    return *(unsigned*)&t;
}
__device__ __forceinline__ void mma_f16(float* d, const unsigned* a, const unsigned* b, const float* c) {
    asm volatile(
        "mma.sync.aligned.m16n8k16.row.col.f32.f16.f16.f32 "
        "{%0,%1,%2,%3}, {%4,%5,%6,%7}, {%8,%9}, {%10,%11,%12,%13};\n"
        : "=f"(d[0]), "=f"(d[1]), "=f"(d[2]), "=f"(d[3])
        : "r"(a[0]), "r"(a[1]), "r"(a[2]), "r"(a[3]),
          "r"(b[0]), "r"(b[1]),
          "f"(c[0]), "f"(c[1]), "f"(c[2]), "f"(c[3]));
}
__device__ __forceinline__ void ldsm_x4(unsigned* r, unsigned addr) {
    asm volatile("ldmatrix.sync.aligned.m8n8.x4.shared.b16 {%0,%1,%2,%3}, [%4];"
        : "=r"(r[0]), "=r"(r[1]), "=r"(r[2]), "=r"(r[3]) : "r"(addr));
}

__device__ __forceinline__ void cp_async16(void* smem, const void* gmem) {
    unsigned s = (unsigned)__cvta_generic_to_shared(smem);
    asm volatile("cp.async.cg.shared.global [%0], [%1], 16;\n" :: "r"(s), "l"(gmem));
}
__device__ __forceinline__ void cp_commit() { asm volatile("cp.async.commit_group;\n"); }
template<int N> __device__ __forceinline__ void cp_wait() {
    asm volatile("cp.async.wait_group %0;\n" :: "n"(N));
}

// ---------------- prepass: x split ----------------
__global__ void split_x_kernel(const float* __restrict__ src, __half* __restrict__ hi,
                               __half* __restrict__ lo, int n) {
    int i = blockIdx.x * blockDim.x + threadIdx.x;
    if (i >= n) return;
    split_h(src[i], hi[i], lo[i]);
}

// ---------------- prepass: weight transpose + split -> Wt[n][k] ----------------
__global__ void wtrans_kernel(const float* __restrict__ w0, const float* __restrict__ w1,
                              const float* __restrict__ w2, const float* __restrict__ w3,
                              __half* __restrict__ hi, __half* __restrict__ lo) {
    __shared__ float t[32][33];
    int w = blockIdx.z;
    const float* W = (w == 0) ? w0 : (w == 1) ? w1 : (w == 2) ? w2 : w3;
    int k0 = blockIdx.x * 32, n0 = blockIdx.y * 32;
    int tx = threadIdx.x, ty = threadIdx.y;
    t[ty][tx] = W[(size_t)(k0 + ty) * DMODEL + n0 + tx];
    __syncthreads();
    float v = t[tx][ty];
    size_t o = (size_t)w * WELEM + (size_t)(n0 + ty) * DMODEL + k0 + tx;
    split_h(v, hi[o], lo[o]);
}

// ---------------- prepass: V transpose + split -> vt[b][dglobal][t] ----------------
__global__ void vtrans_kernel(const float* __restrict__ vraw,
                              __half* __restrict__ hi, __half* __restrict__ lo) {
    __shared__ float t[32][33];
    int b = blockIdx.z;
    int t0 = blockIdx.x * 32, d0 = blockIdx.y * 32;
    int tx = threadIdx.x, ty = threadIdx.y;
    t[ty][tx] = vraw[(size_t)(b * SEQ + t0 + ty) * DMODEL + d0 + tx];
    __syncthreads();
    float v = t[tx][ty];
    size_t o = ((size_t)b * DMODEL + d0 + ty) * SEQ + t0 + tx;
    split_h(v, hi[o], lo[o]);
}

// ---------------- RoPE table ----------------
__global__ void rope_table_kernel(float* ct, float* st) {
    int idx = blockIdx.x * blockDim.x + threadIdx.x;
    if (idx >= SEQ * (HDIM/2)) return;
    int t = idx >> 5;
    int i = idx & 31;
    float inv_freq = powf(10000.0f, -(float)(2 * i) / (float)HDIM);
    float ang = (float)t * inv_freq;
    ct[idx] = cosf(ang);
    st[idx] = sinf(ang);
}

// ---------------- FP16-emulated GEMM (80B stride, 2-stage) ----------------
// mode 0 (QKV): z=0 q -> 3-term, rope+0.125, store hi+lo
//               z=1 k -> 3-term, rope, store hi ONLY
//               z=2 v -> 2-term (Ah*(Bh+Bl)), f32 store
// mode 1 (Wo):  2-term, plain f32 store.
#define GEMM_SMEM 81920

__global__ __launch_bounds__(256, 2)
void gemm_f16_kernel(const __half* __restrict__ Ah, const __half* __restrict__ Al,
                     const __half* __restrict__ B0h, const __half* __restrict__ B0l,
                     const __half* __restrict__ B1h, const __half* __restrict__ B1l,
                     const __half* __restrict__ B2h, const __half* __restrict__ B2l,
                     const float* __restrict__ ct, const float* __restrict__ st,
                     __half* __restrict__ qh, __half* __restrict__ ql,
                     __half* __restrict__ kh,
                     float* __restrict__ vout, float* __restrict__ Cplain, int mode) {
    const int K = DMODEL;
    extern __shared__ __half smh[];

    int z = blockIdx.z;
    const __half* Bh = (z == 0) ? B0h : (z == 1) ? B1h : B2h;
    const __half* Bl = (z == 0) ? B0l : (z == 1) ? B1l : B2l;
    bool use_al = (mode == 0) && (z != 2);

    int tid  = threadIdx.x;
    int wid  = tid >> 5, lane = tid & 31;
    int g = lane >> 2, c = lane & 3;
    int wm = (wid & 3) * 32;
    int wn = (wid >> 2) * 64;
    int bm = blockIdx.y * 128, bn = blockIdx.x * 128;

    int lrow = tid >> 1, lseg = (tid & 1) * 16;

    unsigned smem_u = (unsigned)__cvta_generic_to_shared(smh);
    unsigned a_frag = smem_u + ((wm + (lane & 15)) * 40 + ((lane & 16) ? 8 : 0)) * 2;
    unsigned b_frag = smem_u + 40960 +
                      ((wn + (lane & 7) + ((lane & 16) ? 8 : 0)) * 40 + ((lane & 8) ? 8 : 0)) * 2;

    float acc[2][8][4];
#pragma unroll
    for (int mf = 0; mf < 2; mf++)
#pragma unroll
        for (int nf = 0; nf < 8; nf++)
#pragma unroll
            for (int j = 0; j < 4; j++) acc[mf][nf][j] = 0.0f;

    auto load_chunk = [&](int buf, int k0) {
        size_t ga = (size_t)(bm + lrow) * K + k0 + lseg;
        __half* da_h = smh + buf * 5120 + lrow * 40 + lseg;
        cp_async16(da_h,     Ah + ga);
        cp_async16(da_h + 8, Ah + ga + 8);
        if (use_al) {
            __half* da_l = da_h + 10240;
            cp_async16(da_l,     Al + ga);
            cp_async16(da_l + 8, Al + ga + 8);
        }
        size_t gb = (size_t)(bn + lrow) * K + k0 + lseg;
        __half* db_h = smh + 20480 + buf * 5120 + lrow * 40 + lseg;
        __half* db_l = db_h + 10240;
        cp_async16(db_h,     Bh + gb);
        cp_async16(db_h + 8, Bh + gb + 8);
        cp_async16(db_l,     Bl + gb);
        cp_async16(db_l + 8, Bl + gb + 8);
    };

    const int NCH = K / 32;  // 24
    load_chunk(0, 0); cp_commit();

    for (int ch = 0; ch < NCH; ch++) {
        int buf = ch & 1;
        if (ch + 1 < NCH) { load_chunk(buf ^ 1, (ch + 1) * 32); cp_commit(); cp_wait<1>(); }
        else              { cp_wait<0>(); }
        __syncthreads();

        unsigned abase = a_frag + buf * 10240;
        unsigned bbase = b_frag + buf * 10240;
#pragma unroll
        for (int ks = 0; ks < 2; ks++) {
            int kb = ks * 32;
            unsigned afh[2][4], afl[2][4], bfh[8][2], bfl[8][2];
            ldsm_x4(afh[0], abase + kb);
            ldsm_x4(afh[1], abase + 1280 + kb);
            if (use_al) {
                ldsm_x4(afl[0], abase + 20480 + kb);
                ldsm_x4(afl[1], abase + 20480 + 1280 + kb);
            }
#pragma unroll
            for (int p = 0; p < 4; p++) {
                unsigned r[4];
                ldsm_x4(r, bbase + p * 1280 + kb);
                bfh[2*p][0] = r[0]; bfh[2*p][1] = r[1]; bfh[2*p+1][0] = r[2]; bfh[2*p+1][1] = r[3];
                ldsm_x4(r, bbase + 20480 + p * 1280 + kb);
                bfl[2*p][0] = r[0]; bfl[2*p][1] = r[1]; bfl[2*p+1][0] = r[2]; bfl[2*p+1][1] = r[3];
            }
#pragma unroll
            for (int mf = 0; mf < 2; mf++)
#pragma unroll
                for (int nf = 0; nf < 8; nf++) {
                    if (use_al) mma_f16(acc[mf][nf], afl[mf], bfh[nf], acc[mf][nf]);
                    mma_f16(acc[mf][nf], afh[mf], bfl[nf], acc[mf][nf]);
                    mma_f16(acc[mf][nf], afh[mf], bfh[nf], acc[mf][nf]);
                }
        }
        __syncthreads();
    }

    // ---------------- epilogue ----------------
    if (mode == 1) {
#pragma unroll
        for (int mf = 0; mf < 2; mf++) {
            int row0 = bm + wm + mf * 16 + g;
#pragma unroll
            for (int nf = 0; nf < 8; nf++) {
                int col = bn + wn + nf * 8 + 2 * c;
                *(float2*)(Cplain + (size_t)row0 * DMODEL + col)       = make_float2(acc[mf][nf][0], acc[mf][nf][1]);
                *(float2*)(Cplain + (size_t)(row0 + 8) * DMODEL + col) = make_float2(acc[mf][nf][2], acc[mf][nf][3]);
            }
        }
        return;
    }
    if (z == 2) {
#pragma unroll
        for (int mf = 0; mf < 2; mf++) {
            int row0 = bm + wm + mf * 16 + g;
#pragma unroll
            for (int nf = 0; nf < 8; nf++) {
                int col = bn + wn + nf * 8 + 2 * c;
                *(float2*)(vout + (size_t)row0 * DMODEL + col)       = make_float2(acc[mf][nf][0], acc[mf][nf][1]);
                *(float2*)(vout + (size_t)(row0 + 8) * DMODEL + col) = make_float2(acc[mf][nf][2], acc[mf][nf][3]);
            }
        }
        return;
    }
    // z==0 (q): rope+scale, store hi+lo.  z==1 (k): rope, store hi only.
    {
        bool isq = (z == 0);
        __half* oh_ = isq ? qh : kh;
        float scale = isq ? 0.125f : 1.0f;
#pragma unroll
        for (int mf = 0; mf < 2; mf++) {
#pragma unroll
            for (int rs = 0; rs < 2; rs++) {
                int row = bm + wm + mf * 16 + g + rs * 8;
                int t = row & (SEQ - 1);
#pragma unroll
                for (int nf = 0; nf < 4; nf++) {
                    int i0 = nf * 8 + 2 * c;
                    float a0 = acc[mf][nf][rs * 2 + 0];
                    float a1 = acc[mf][nf][rs * 2 + 1];
                    float b0 = acc[mf][nf + 4][rs * 2 + 0];
                    float b1 = acc[mf][nf + 4][rs * 2 + 1];
                    float c0 = ct[t * 32 + i0],     s0 = st[t * 32 + i0];
                    float c1 = ct[t * 32 + i0 + 1], s1 = st[t * 32 + i0 + 1];
                    float rA0 = (a0 * c0 - b0 * s0) * scale;
                    float rB0 = (a0 * s0 + b0 * c0) * scale;
                    float rA1 = (a1 * c1 - b1 * s1) * scale;
                    float rB1 = (a1 * s1 + b1 * c1) * scale;
                    size_t o = (size_t)row * DMODEL + bn + wn + i0;
                    if (isq) {
                        __half hA0, lA0, hA1, lA1, hB0, lB0, hB1, lB1;
                        split_h(rA0, hA0, lA0); split_h(rA1, hA1, lA1);
                        split_h(rB0, hB0, lB0); split_h(rB1, hB1, lB1);
                        *(unsigned*)&oh_[o]      = pack2(hA0, hA1);
                        *(unsigned*)&ql[o]       = pack2(lA0, lA1);
                        *(unsigned*)&oh_[o + 32] = pack2(hB0, hB1);
                        *(unsigned*)&ql[o + 32]  = pack2(lB0, lB1);
                    } else {
                        *(unsigned*)&oh_[o]      = pack2(__float2half_rn(rA0), __float2half_rn(rA1));
                        *(unsigned*)&oh_[o + 32] = pack2(__float2half_rn(rB0), __float2half_rn(rB1));
                    }
                }
            }
        }
    }
}

// ---------------- causal flash attention: 2-term S (K fp16), 2-term PV ----------------
#define HTSZ (64 * 72)                 // halves per tile (144B rows, 16B-aligned)
#define HTB  (HTSZ * 2)                // 9216 B
#define ATTN_SMEM (9 * HTB)            // 82944 B : KH[3] | VH[3] | VL[3]

__global__ __launch_bounds__(256, 2)
void attn_f16_kernel(const __half* __restrict__ qh, const __half* __restrict__ ql,
                     const __half* __restrict__ kh,
                     const __half* __restrict__ vth, const __half* __restrict__ vtl,
                     __half* __restrict__ oh) {
    extern __shared__ __half sm[];

    int qt = gridDim.x - 1 - blockIdx.x;   // heaviest blocks first
    int h = blockIdx.y, b = blockIdx.z;
    int tid = threadIdx.x;
    int warp = tid >> 5, lane = tid & 31;
    int g = lane >> 2, c = lane & 3;
    int qbase_w = qt * 128 + warp * 16;

    unsigned smem_u = (unsigned)__cvta_generic_to_shared(sm);
    unsigned kv_frag = smem_u + ((lane & 7) + ((lane & 16) ? 8 : 0)) * 144 + ((lane & 8) ? 16 : 0);

    unsigned qfh[4][4], qfl[4][4];
    {
        size_t b0 = (size_t)(b * SEQ + qbase_w + g)     * DMODEL + h * HDIM;
        size_t b1 = (size_t)(b * SEQ + qbase_w + g + 8) * DMODEL + h * HDIM;
#pragma unroll
        for (int ks = 0; ks < 4; ks++) {
            int k0 = ks * 16 + 2 * c;
            qfh[ks][0] = *(const unsigned*)&qh[b0 + k0];
            qfh[ks][1] = *(const unsigned*)&qh[b1 + k0];
            qfh[ks][2] = *(const unsigned*)&qh[b0 + k0 + 8];
            qfh[ks][3] = *(const unsigned*)&qh[b1 + k0 + 8];
            qfl[ks][0] = *(const unsigned*)&ql[b0 + k0];
            qfl[ks][1] = *(const unsigned*)&ql[b1 + k0];
            qfl[ks][2] = *(const unsigned*)&ql[b0 + k0 + 8];
            qfl[ks][3] = *(const unsigned*)&ql[b1 + k0 + 8];
        }
    }

    float oacc[8][4];
#pragma unroll
    for (int nf = 0; nf < 8; nf++)
#pragma unroll
        for (int j = 0; j < 4; j++) oacc[nf][j] = 0.0f;
    float m0 = -1e30f, m1 = -1e30f, l0 = 0.0f, l1 = 0.0f;
    int qr0 = qbase_w + g;
    int qr1 = qr0 + 8;

    auto load_kv = [&](int buf, int kt) {
        size_t kb_ = (size_t)(b * SEQ + kt * 64) * DMODEL + h * HDIM;
        size_t vb_ = ((size_t)b * DMODEL + h * HDIM) * SEQ + kt * 64;
        __half* dkh = sm + buf * HTSZ;
        __half* dvh = sm + (3 + buf) * HTSZ;
        __half* dvl = sm + (6 + buf) * HTSZ;
#pragma unroll
        for (int i = tid; i < 64 * 8; i += 256) {
            int row = i >> 3, seg = (i & 7) * 8;
            int so = row * 72 + seg;
            cp_async16(dkh + so, kh  + kb_ + (size_t)row * DMODEL + seg);
            cp_async16(dvh + so, vth + vb_ + (size_t)row * SEQ    + seg);
            cp_async16(dvl + so, vtl + vb_ + (size_t)row * SEQ    + seg);
        }
    };

    const int kt_max = 2 * qt + 1;
    load_kv(0, 0); cp_commit();
    if (kt_max >= 1) { load_kv(1, 1); cp_commit(); }

    for (int kt = 0; kt <= kt_max; kt++) {
        int buf = kt % 3;
        if (kt < kt_max) cp_wait<1>(); else cp_wait<0>();
        __syncthreads();
        if (kt + 2 <= kt_max) { load_kv((kt + 2) % 3, kt + 2); cp_commit(); }

        int rel = qbase_w + 15 - kt * 64;
        int nblk = (rel < 0) ? 0 : min(8, (rel >> 3) + 1);
        int nblkS = (nblk + 1) & ~1;
        bool need_mask = (kt * 64 + 63 > qbase_w);

        if (nblkS > 0) {
            unsigned kh_b = kv_frag + buf * HTB;

            // S = Q K^T  (2-term: (qh+ql)·kh)
            float sc[8][4];
            int npair = nblkS >> 1;
            for (int p = 0; p < npair; p++) {
#pragma unroll
                for (int j = 0; j < 4; j++) { sc[2*p][j] = 0.0f; sc[2*p+1][j] = 0.0f; }
#pragma unroll
                for (int ks = 0; ks < 4; ks++) {
                    unsigned bh[4];
                    ldsm_x4(bh, kh_b + p * 2304 + ks * 32);
                    mma_f16(sc[2*p],   qfl[ks], bh,     sc[2*p]);
                    mma_f16(sc[2*p],   qfh[ks], bh,     sc[2*p]);
                    mma_f16(sc[2*p+1], qfl[ks], bh + 2, sc[2*p+1]);
                    mma_f16(sc[2*p+1], qfh[ks], bh + 2, sc[2*p+1]);
                }
            }

            if (need_mask) {
                for (int nf = 0; nf < nblkS; nf++) {
#pragma unroll
                    for (int j = 0; j < 4; j++) {
                        int key = kt * 64 + nf * 8 + 2 * c + (j & 1);
                        int qr  = (j < 2) ? qr0 : qr1;
                        if (key > qr) sc[nf][j] = -1e30f;
                    }
                }
            }

            float mx0 = -1e30f, mx1 = -1e30f;
            for (int nf = 0; nf < nblkS; nf++) {
                mx0 = fmaxf(mx0, fmaxf(sc[nf][0], sc[nf][1]));
                mx1 = fmaxf(mx1, fmaxf(sc[nf][2], sc[nf][3]));
            }
            mx0 = fmaxf(mx0, __shfl_xor_sync(0xffffffffu, mx0, 1));
            mx0 = fmaxf(mx0, __shfl_xor_sync(0xffffffffu, mx0, 2));
            mx1 = fmaxf(mx1, __shfl_xor_sync(0xffffffffu, mx1, 1));
            mx1 = fmaxf(mx1, __shfl_xor_sync(0xffffffffu, mx1, 2));
            float nm0 = fmaxf(m0, mx0), nm1 = fmaxf(m1, mx1);
            float cor0 = __expf(m0 - nm0), cor1 = __expf(m1 - nm1);
            m0 = nm0; m1 = nm1;
            l0 *= cor0; l1 *= cor1;
#pragma unroll
            for (int nf = 0; nf < 8; nf++) {
                oacc[nf][0] *= cor0; oacc[nf][1] *= cor0;
                oacc[nf][2] *= cor1; oacc[nf][3] *= cor1;
            }
            for (int nf = 0; nf < nblkS; nf++) {
                sc[nf][0] = __expf(sc[nf][0] - m0);
                sc[nf][1] = __expf(sc[nf][1] - m0);
                sc[nf][2] = __expf(sc[nf][2] - m1);
                sc[nf][3] = __expf(sc[nf][3] - m1);
                l0 += sc[nf][0] + sc[nf][1];
                l1 += sc[nf][2] + sc[nf][3];
            }

            // O += P V  (2-term: P fp16, V 22-bit)
            unsigned vh_b = kv_frag + (3 + buf) * HTB;
            unsigned vl_b = kv_frag + (6 + buf) * HTB;
            int nkb = nblkS >> 1;
            for (int kb = 0; kb < nkb; kb++) {
                unsigned ah[4];
                ah[0] = pack2(__float2half_rn(sc[2*kb][0]),   __float2half_rn(sc[2*kb][1]));
                ah[1] = pack2(__float2half_rn(sc[2*kb][2]),   __float2half_rn(sc[2*kb][3]));
                ah[2] = pack2(__float2half_rn(sc[2*kb+1][0]), __float2half_rn(sc[2*kb+1][1]));
                ah[3] = pack2(__float2half_rn(sc[2*kb+1][2]), __float2half_rn(sc[2*kb+1][3]));
#pragma unroll
                for (int p = 0; p < 4; p++) {
                    unsigned bh[4], bl[4];
                    ldsm_x4(bh, vh_b + p * 2304 + kb * 32);
                    ldsm_x4(bl, vl_b + p * 2304 + kb * 32);
                    mma_f16(oacc[2*p],   ah, bl,     oacc[2*p]);
                    mma_f16(oacc[2*p],   ah, bh,     oacc[2*p]);
                    mma_f16(oacc[2*p+1], ah, bl + 2, oacc[2*p+1]);
                    mma_f16(oacc[2*p+1], ah, bh + 2, oacc[2*p+1]);
                }
            }
        }
    }

    l0 += __shfl_xor_sync(0xffffffffu, l0, 1);
    l0 += __shfl_xor_sync(0xffffffffu, l0, 2);
    l1 += __shfl_xor_sync(0xffffffffu, l1, 1);
    l1 += __shfl_xor_sync(0xffffffffu, l1, 2);
    float inv0 = 1.0f / l0, inv1 = 1.0f / l1;

    size_t o0 = (size_t)(b * SEQ + qr0) * DMODEL + h * HDIM;
    size_t o1 = (size_t)(b * SEQ + qr1) * DMODEL + h * HDIM;
#pragma unroll
    for (int nf = 0; nf < 8; nf++) {
        int col = nf * 8 + 2 * c;
        *(unsigned*)&oh[o0 + col] = pack2(__float2half_rn(oacc[nf][0] * inv0),
                                          __float2half_rn(oacc[nf][1] * inv0));
        *(unsigned*)&oh[o1 + col] = pack2(__float2half_rn(oacc[nf][2] * inv1),
                                          __float2half_rn(oacc[nf][3] * inv1));
    }
}

// ---------------- launch ----------------
extern "C" void kernel_launch(void* const* d_in, const int* in_sizes, int n_in,
                              void* d_out, int out_size) {
    const float* x  = (const float*)d_in[0];
    const float* Wq = (const float*)d_in[1];
    const float* Wk = (const float*)d_in[2];
    const float* Wv = (const float*)d_in[3];
    const float* Wo = (const float*)d_in[4];
    float* out = (float*)d_out;

    cudaFuncSetAttribute(gemm_f16_kernel, cudaFuncAttributeMaxDynamicSharedMemorySize, GEMM_SMEM);
    cudaFuncSetAttribute(attn_f16_kernel, cudaFuncAttributeMaxDynamicSharedMemorySize, ATTN_SMEM);

    __half *xh, *xl, *wth, *wtl, *qh, *ql, *kh, *vth, *vtl, *ath;
    float *vraw, *ct, *st;
    cudaGetSymbolAddress((void**)&xh,   g_xh);
    cudaGetSymbolAddress((void**)&xl,   g_xl);
    cudaGetSymbolAddress((void**)&wth,  g_wth);
    cudaGetSymbolAddress((void**)&wtl,  g_wtl);
    cudaGetSymbolAddress((void**)&vraw, g_vraw);
    cudaGetSymbolAddress((void**)&qh,   g_qh);
    cudaGetSymbolAddress((void**)&ql,   g_ql);
    cudaGetSymbolAddress((void**)&kh,   g_kh);
    cudaGetSymbolAddress((void**)&vth,  g_vth);
    cudaGetSymbolAddress((void**)&vtl,  g_vtl);
    cudaGetSymbolAddress((void**)&ath,  g_ath);
    cudaGetSymbolAddress((void**)&ct,   g_cos);
    cudaGetSymbolAddress((void**)&st,   g_sin);

    {
        int n = SEQ * (HDIM/2);
        rope_table_kernel<<<(n + 255) / 256, 256>>>(ct, st);
    }

    split_x_kernel<<<(NELEM + 255) / 256, 256>>>(x, xh, xl, NELEM);
    wtrans_kernel<<<dim3(DMODEL/32, DMODEL/32, 4), dim3(32, 32)>>>(Wq, Wk, Wv, Wo, wth, wtl);

    // merged QKV projection with fused rope epilogue
    dim3 qkv_grid(DMODEL / 128, MROWS / 128, 3);
    gemm_f16_kernel<<<qkv_grid, 256, GEMM_SMEM>>>(xh, xl,
                                    wth + 0 * WELEM, wtl + 0 * WELEM,
                                    wth + 1 * WELEM, wtl + 1 * WELEM,
                                    wth + 2 * WELEM, wtl + 2 * WELEM,
                                    ct, st, qh, ql, kh, vraw, nullptr, 0);

    vtrans_kernel<<<dim3(SEQ/32, DMODEL/32, BATCH), dim3(32, 32)>>>(vraw, vth, vtl);

    attn_f16_kernel<<<dim3(SEQ / 128, NHEADS, BATCH), 256, ATTN_SMEM>>>(
        qh, ql, kh, vth, vtl, ath);

    // output projection (2-term)
    dim3 o_grid(DMODEL / 128, MROWS / 128, 1);
    gemm_f16_kernel<<<o_grid, 256, GEMM_SMEM>>>(ath, ath,
                                  wth + 3 * WELEM, wtl + 3 * WELEM,
                                  wth + 3 * WELEM, wtl + 3 * WELEM,
                                  wth + 3 * WELEM, wtl + 3 * WELEM,
                                  ct, st, nullptr, nullptr, nullptr, nullptr, out, 1);
}

// round 16
// speedup vs baseline: 1.3056x; 1.0496x over previous
#include <cuda_runtime.h>
#include <cuda_fp16.h>
#include <cstdint>
#include <math.h>

#define BATCH 2
#define SEQ   2048
#define DMODEL 768
#define NHEADS 12
#define HDIM  64
#define MROWS (BATCH*SEQ)   // 4096
#define NELEM (MROWS*DMODEL)
#define WELEM (DMODEL*DMODEL)

// ---------------- scratch (device globals; allocation-free) ----------------
__device__ __half g_xh[NELEM],  g_xl[NELEM];
__device__ __half g_wth[4][WELEM], g_wtl[4][WELEM];   // transposed [n][k]
__device__ float  g_vraw[NELEM];
__device__ __half g_qh[NELEM];                         // Q fp16-only
__device__ __half g_kh[NELEM];                         // K fp16-only
__device__ __half g_vth[NELEM], g_vtl[NELEM];          // [b][dglobal][t]
__device__ __half g_ath[NELEM];                        // attention out (fp16 only)
__device__ float  g_cos[SEQ * (HDIM/2)];
__device__ float  g_sin[SEQ * (HDIM/2)];

// ---------------- fp16-split helpers ----------------
__device__ __forceinline__ void split_h(float x, __half& h, __half& l) {
    h = __float2half_rn(x);
    l = __float2half_rn(x - __half2float(h));
}
__device__ __forceinline__ unsigned pack2(__half a, __half b) {
    __half2 t = __halves2half2(a, b);
    return *(unsigned*)&t;
}
__device__ __forceinline__ void mma_f16(float* d, const unsigned* a, const unsigned* b, const float* c) {
    asm volatile(
        "mma.sync.aligned.m16n8k16.row.col.f32.f16.f16.f32 "
        "{%0,%1,%2,%3}, {%4,%5,%6,%7}, {%8,%9}, {%10,%11,%12,%13};\n"
        : "=f"(d[0]), "=f"(d[1]), "=f"(d[2]), "=f"(d[3])
        : "r"(a[0]), "r"(a[1]), "r"(a[2]), "r"(a[3]),
          "r"(b[0]), "r"(b[1]),
          "f"(c[0]), "f"(c[1]), "f"(c[2]), "f"(c[3]));
}
__device__ __forceinline__ void ldsm_x4(unsigned* r, unsigned addr) {
    asm volatile("ldmatrix.sync.aligned.m8n8.x4.shared.b16 {%0,%1,%2,%3}, [%4];"
        : "=r"(r[0]), "=r"(r[1]), "=r"(r[2]), "=r"(r[3]) : "r"(addr));
}

__device__ __forceinline__ void cp_async16(void* smem, const void* gmem) {
    unsigned s = (unsigned)__cvta_generic_to_shared(smem);
    asm volatile("cp.async.cg.shared.global [%0], [%1], 16;\n" :: "r"(s), "l"(gmem));
}
__device__ __forceinline__ void cp_commit() { asm volatile("cp.async.commit_group;\n"); }
template<int N> __device__ __forceinline__ void cp_wait() {
    asm volatile("cp.async.wait_group %0;\n" :: "n"(N));
}

// ---------------- prepass: x split ----------------
__global__ void split_x_kernel(const float* __restrict__ src, __half* __restrict__ hi,
                               __half* __restrict__ lo, int n) {
    int i = blockIdx.x * blockDim.x + threadIdx.x;
    if (i >= n) return;
    split_h(src[i], hi[i], lo[i]);
}

// ---------------- prepass: weight transpose + split -> Wt[n][k] ----------------
__global__ void wtrans_kernel(const float* __restrict__ w0, const float* __restrict__ w1,
                              const float* __restrict__ w2, const float* __restrict__ w3,
                              __half* __restrict__ hi, __half* __restrict__ lo) {
    __shared__ float t[32][33];
    int w = blockIdx.z;
    const float* W = (w == 0) ? w0 : (w == 1) ? w1 : (w == 2) ? w2 : w3;
    int k0 = blockIdx.x * 32, n0 = blockIdx.y * 32;
    int tx = threadIdx.x, ty = threadIdx.y;
    t[ty][tx] = W[(size_t)(k0 + ty) * DMODEL + n0 + tx];
    __syncthreads();
    float v = t[tx][ty];
    size_t o = (size_t)w * WELEM + (size_t)(n0 + ty) * DMODEL + k0 + tx;
    split_h(v, hi[o], lo[o]);
}

// ---------------- prepass: V transpose + split -> vt[b][dglobal][t] ----------------
__global__ void vtrans_kernel(const float* __restrict__ vraw,
                              __half* __restrict__ hi, __half* __restrict__ lo) {
    __shared__ float t[32][33];
    int b = blockIdx.z;
    int t0 = blockIdx.x * 32, d0 = blockIdx.y * 32;
    int tx = threadIdx.x, ty = threadIdx.y;
    t[ty][tx] = vraw[(size_t)(b * SEQ + t0 + ty) * DMODEL + d0 + tx];
    __syncthreads();
    float v = t[tx][ty];
    size_t o = ((size_t)b * DMODEL + d0 + ty) * SEQ + t0 + tx;
    split_h(v, hi[o], lo[o]);
}

// ---------------- RoPE table ----------------
__global__ void rope_table_kernel(float* ct, float* st) {
    int idx = blockIdx.x * blockDim.x + threadIdx.x;
    if (idx >= SEQ * (HDIM/2)) return;
    int t = idx >> 5;
    int i = idx & 31;
    float inv_freq = powf(10000.0f, -(float)(2 * i) / (float)HDIM);
    float ang = (float)t * inv_freq;
    ct[idx] = cosf(ang);
    st[idx] = sinf(ang);
}

// ---------------- FP16-emulated GEMM (80B stride, 2-stage) ----------------
// mode 0 (QKV): z=0 q -> 3-term, rope+0.125, store fp16
//               z=1 k -> 3-term, rope, store fp16
//               z=2 v -> 2-term (Ah*(Bh+Bl)), f32 store
// mode 1 (Wo):  2-term, plain f32 store.
#define GEMM_SMEM 81920

__global__ __launch_bounds__(256, 2)
void gemm_f16_kernel(const __half* __restrict__ Ah, const __half* __restrict__ Al,
                     const __half* __restrict__ B0h, const __half* __restrict__ B0l,
                     const __half* __restrict__ B1h, const __half* __restrict__ B1l,
                     const __half* __restrict__ B2h, const __half* __restrict__ B2l,
                     const float* __restrict__ ct, const float* __restrict__ st,
                     __half* __restrict__ qh, __half* __restrict__ kh,
                     float* __restrict__ vout, float* __restrict__ Cplain, int mode) {
    const int K = DMODEL;
    extern __shared__ __half smh[];

    int z = blockIdx.z;
    const __half* Bh = (z == 0) ? B0h : (z == 1) ? B1h : B2h;
    const __half* Bl = (z == 0) ? B0l : (z == 1) ? B1l : B2l;
    bool use_al = (mode == 0) && (z != 2);

    int tid  = threadIdx.x;
    int wid  = tid >> 5, lane = tid & 31;
    int g = lane >> 2, c = lane & 3;
    int wm = (wid & 3) * 32;
    int wn = (wid >> 2) * 64;
    int bm = blockIdx.y * 128, bn = blockIdx.x * 128;

    int lrow = tid >> 1, lseg = (tid & 1) * 16;

    unsigned smem_u = (unsigned)__cvta_generic_to_shared(smh);
    unsigned a_frag = smem_u + ((wm + (lane & 15)) * 40 + ((lane & 16) ? 8 : 0)) * 2;
    unsigned b_frag = smem_u + 40960 +
                      ((wn + (lane & 7) + ((lane & 16) ? 8 : 0)) * 40 + ((lane & 8) ? 8 : 0)) * 2;

    float acc[2][8][4];
#pragma unroll
    for (int mf = 0; mf < 2; mf++)
#pragma unroll
        for (int nf = 0; nf < 8; nf++)
#pragma unroll
            for (int j = 0; j < 4; j++) acc[mf][nf][j] = 0.0f;

    auto load_chunk = [&](int buf, int k0) {
        size_t ga = (size_t)(bm + lrow) * K + k0 + lseg;
        __half* da_h = smh + buf * 5120 + lrow * 40 + lseg;
        cp_async16(da_h,     Ah + ga);
        cp_async16(da_h + 8, Ah + ga + 8);
        if (use_al) {
            __half* da_l = da_h + 10240;
            cp_async16(da_l,     Al + ga);
            cp_async16(da_l + 8, Al + ga + 8);
        }
        size_t gb = (size_t)(bn + lrow) * K + k0 + lseg;
        __half* db_h = smh + 20480 + buf * 5120 + lrow * 40 + lseg;
        __half* db_l = db_h + 10240;
        cp_async16(db_h,     Bh + gb);
        cp_async16(db_h + 8, Bh + gb + 8);
        cp_async16(db_l,     Bl + gb);
        cp_async16(db_l + 8, Bl + gb + 8);
    };

    const int NCH = K / 32;  // 24
    load_chunk(0, 0); cp_commit();

    for (int ch = 0; ch < NCH; ch++) {
        int buf = ch & 1;
        if (ch + 1 < NCH) { load_chunk(buf ^ 1, (ch + 1) * 32); cp_commit(); cp_wait<1>(); }
        else              { cp_wait<0>(); }
        __syncthreads();

        unsigned abase = a_frag + buf * 10240;
        unsigned bbase = b_frag + buf * 10240;
#pragma unroll
        for (int ks = 0; ks < 2; ks++) {
            int kb = ks * 32;
            unsigned afh[2][4], afl[2][4], bfh[8][2], bfl[8][2];
            ldsm_x4(afh[0], abase + kb);
            ldsm_x4(afh[1], abase + 1280 + kb);
            if (use_al) {
                ldsm_x4(afl[0], abase + 20480 + kb);
                ldsm_x4(afl[1], abase + 20480 + 1280 + kb);
            }
#pragma unroll
            for (int p = 0; p < 4; p++) {
                unsigned r[4];
                ldsm_x4(r, bbase + p * 1280 + kb);
                bfh[2*p][0] = r[0]; bfh[2*p][1] = r[1]; bfh[2*p+1][0] = r[2]; bfh[2*p+1][1] = r[3];
                ldsm_x4(r, bbase + 20480 + p * 1280 + kb);
                bfl[2*p][0] = r[0]; bfl[2*p][1] = r[1]; bfl[2*p+1][0] = r[2]; bfl[2*p+1][1] = r[3];
            }
#pragma unroll
            for (int mf = 0; mf < 2; mf++)
#pragma unroll
                for (int nf = 0; nf < 8; nf++) {
                    if (use_al) mma_f16(acc[mf][nf], afl[mf], bfh[nf], acc[mf][nf]);
                    mma_f16(acc[mf][nf], afh[mf], bfl[nf], acc[mf][nf]);
                    mma_f16(acc[mf][nf], afh[mf], bfh[nf], acc[mf][nf]);
                }
        }
        __syncthreads();
    }

    // ---------------- epilogue ----------------
    if (mode == 1) {
#pragma unroll
        for (int mf = 0; mf < 2; mf++) {
            int row0 = bm + wm + mf * 16 + g;
#pragma unroll
            for (int nf = 0; nf < 8; nf++) {
                int col = bn + wn + nf * 8 + 2 * c;
                *(float2*)(Cplain + (size_t)row0 * DMODEL + col)       = make_float2(acc[mf][nf][0], acc[mf][nf][1]);
                *(float2*)(Cplain + (size_t)(row0 + 8) * DMODEL + col) = make_float2(acc[mf][nf][2], acc[mf][nf][3]);
            }
        }
        return;
    }
    if (z == 2) {
#pragma unroll
        for (int mf = 0; mf < 2; mf++) {
            int row0 = bm + wm + mf * 16 + g;
#pragma unroll
            for (int nf = 0; nf < 8; nf++) {
                int col = bn + wn + nf * 8 + 2 * c;
                *(float2*)(vout + (size_t)row0 * DMODEL + col)       = make_float2(acc[mf][nf][0], acc[mf][nf][1]);
                *(float2*)(vout + (size_t)(row0 + 8) * DMODEL + col) = make_float2(acc[mf][nf][2], acc[mf][nf][3]);
            }
        }
        return;
    }
    // z==0 (q, scale 0.125) or z==1 (k): rope, store fp16
    {
        bool isq = (z == 0);
        __half* oh_ = isq ? qh : kh;
        float scale = isq ? 0.125f : 1.0f;
#pragma unroll
        for (int mf = 0; mf < 2; mf++) {
#pragma unroll
            for (int rs = 0; rs < 2; rs++) {
                int row = bm + wm + mf * 16 + g + rs * 8;
                int t = row & (SEQ - 1);
#pragma unroll
                for (int nf = 0; nf < 4; nf++) {
                    int i0 = nf * 8 + 2 * c;
                    float a0 = acc[mf][nf][rs * 2 + 0];
                    float a1 = acc[mf][nf][rs * 2 + 1];
                    float b0 = acc[mf][nf + 4][rs * 2 + 0];
                    float b1 = acc[mf][nf + 4][rs * 2 + 1];
                    float c0 = ct[t * 32 + i0],     s0 = st[t * 32 + i0];
                    float c1 = ct[t * 32 + i0 + 1], s1 = st[t * 32 + i0 + 1];
                    float rA0 = (a0 * c0 - b0 * s0) * scale;
                    float rB0 = (a0 * s0 + b0 * c0) * scale;
                    float rA1 = (a1 * c1 - b1 * s1) * scale;
                    float rB1 = (a1 * s1 + b1 * c1) * scale;
                    size_t o = (size_t)row * DMODEL + bn + wn + i0;
                    *(unsigned*)&oh_[o]      = pack2(__float2half_rn(rA0), __float2half_rn(rA1));
                    *(unsigned*)&oh_[o + 32] = pack2(__float2half_rn(rB0), __float2half_rn(rB1));
                }
            }
        }
    }
}

// ---------------- causal flash attention: 1-term S, 2-term PV ----------------
#define HTSZ (64 * 72)                 // halves per tile (144B rows, 16B-aligned)
#define HTB  (HTSZ * 2)                // 9216 B
#define ATTN_SMEM (9 * HTB)            // 82944 B : KH[3] | VH[3] | VL[3]

__global__ __launch_bounds__(256, 2)
void attn_f16_kernel(const __half* __restrict__ qh,
                     const __half* __restrict__ kh,
                     const __half* __restrict__ vth, const __half* __restrict__ vtl,
                     __half* __restrict__ oh) {
    extern __shared__ __half sm[];

    int qt = gridDim.x - 1 - blockIdx.x;   // heaviest blocks first
    int h = blockIdx.y, b = blockIdx.z;
    int tid = threadIdx.x;
    int warp = tid >> 5, lane = tid & 31;
    int g = lane >> 2, c = lane & 3;
    int qbase_w = qt * 128 + warp * 16;

    unsigned smem_u = (unsigned)__cvta_generic_to_shared(sm);
    unsigned kv_frag = smem_u + ((lane & 7) + ((lane & 16) ? 8 : 0)) * 144 + ((lane & 8) ? 16 : 0);

    unsigned qfh[4][4];
    {
        size_t b0 = (size_t)(b * SEQ + qbase_w + g)     * DMODEL + h * HDIM;
        size_t b1 = (size_t)(b * SEQ + qbase_w + g + 8) * DMODEL + h * HDIM;
#pragma unroll
        for (int ks = 0; ks < 4; ks++) {
            int k0 = ks * 16 + 2 * c;
            qfh[ks][0] = *(const unsigned*)&qh[b0 + k0];
            qfh[ks][1] = *(const unsigned*)&qh[b1 + k0];
            qfh[ks][2] = *(const unsigned*)&qh[b0 + k0 + 8];
            qfh[ks][3] = *(const unsigned*)&qh[b1 + k0 + 8];
        }
    }

    float oacc[8][4];
#pragma unroll
    for (int nf = 0; nf < 8; nf++)
#pragma unroll
        for (int j = 0; j < 4; j++) oacc[nf][j] = 0.0f;
    float m0 = -1e30f, m1 = -1e30f, l0 = 0.0f, l1 = 0.0f;
    int qr0 = qbase_w + g;
    int qr1 = qr0 + 8;

    auto load_kv = [&](int buf, int kt) {
        size_t kb_ = (size_t)(b * SEQ + kt * 64) * DMODEL + h * HDIM;
        size_t vb_ = ((size_t)b * DMODEL + h * HDIM) * SEQ + kt * 64;
        __half* dkh = sm + buf * HTSZ;
        __half* dvh = sm + (3 + buf) * HTSZ;
        __half* dvl = sm + (6 + buf) * HTSZ;
#pragma unroll
        for (int i = tid; i < 64 * 8; i += 256) {
            int row = i >> 3, seg = (i & 7) * 8;
            int so = row * 72 + seg;
            cp_async16(dkh + so, kh  + kb_ + (size_t)row * DMODEL + seg);
            cp_async16(dvh + so, vth + vb_ + (size_t)row * SEQ    + seg);
            cp_async16(dvl + so, vtl + vb_ + (size_t)row * SEQ    + seg);
        }
    };

    const int kt_max = 2 * qt + 1;
    load_kv(0, 0); cp_commit();
    if (kt_max >= 1) { load_kv(1, 1); cp_commit(); }

    for (int kt = 0; kt <= kt_max; kt++) {
        int buf = kt % 3;
        if (kt < kt_max) cp_wait<1>(); else cp_wait<0>();
        __syncthreads();
        if (kt + 2 <= kt_max) { load_kv((kt + 2) % 3, kt + 2); cp_commit(); }

        int rel = qbase_w + 15 - kt * 64;
        int nblk = (rel < 0) ? 0 : min(8, (rel >> 3) + 1);
        int nblkS = (nblk + 1) & ~1;
        bool need_mask = (kt * 64 + 63 > qbase_w);

        if (nblkS > 0) {
            unsigned kh_b = kv_frag + buf * HTB;

            // S = Q K^T  (1-term: qh·kh)
            float sc[8][4];
            int npair = nblkS >> 1;
            for (int p = 0; p < npair; p++) {
#pragma unroll
                for (int j = 0; j < 4; j++) { sc[2*p][j] = 0.0f; sc[2*p+1][j] = 0.0f; }
#pragma unroll
                for (int ks = 0; ks < 4; ks++) {
                    unsigned bh[4];
                    ldsm_x4(bh, kh_b + p * 2304 + ks * 32);
                    mma_f16(sc[2*p],   qfh[ks], bh,     sc[2*p]);
                    mma_f16(sc[2*p+1], qfh[ks], bh + 2, sc[2*p+1]);
                }
            }

            if (need_mask) {
                for (int nf = 0; nf < nblkS; nf++) {
#pragma unroll
                    for (int j = 0; j < 4; j++) {
                        int key = kt * 64 + nf * 8 + 2 * c + (j & 1);
                        int qr  = (j < 2) ? qr0 : qr1;
                        if (key > qr) sc[nf][j] = -1e30f;
                    }
                }
            }

            float mx0 = -1e30f, mx1 = -1e30f;
            for (int nf = 0; nf < nblkS; nf++) {
                mx0 = fmaxf(mx0, fmaxf(sc[nf][0], sc[nf][1]));
                mx1 = fmaxf(mx1, fmaxf(sc[nf][2], sc[nf][3]));
            }
            mx0 = fmaxf(mx0, __shfl_xor_sync(0xffffffffu, mx0, 1));
            mx0 = fmaxf(mx0, __shfl_xor_sync(0xffffffffu, mx0, 2));
            mx1 = fmaxf(mx1, __shfl_xor_sync(0xffffffffu, mx1, 1));
            mx1 = fmaxf(mx1, __shfl_xor_sync(0xffffffffu, mx1, 2));
            float nm0 = fmaxf(m0, mx0), nm1 = fmaxf(m1, mx1);
            float cor0 = __expf(m0 - nm0), cor1 = __expf(m1 - nm1);
            m0 = nm0; m1 = nm1;
            l0 *= cor0; l1 *= cor1;
#pragma unroll
            for (int nf = 0; nf < 8; nf++) {
                oacc[nf][0] *= cor0; oacc[nf][1] *= cor0;
                oacc[nf][2] *= cor1; oacc[nf][3] *= cor1;
            }
            for (int nf = 0; nf < nblkS; nf++) {
                sc[nf][0] = __expf(sc[nf][0] - m0);
                sc[nf][1] = __expf(sc[nf][1] - m0);
                sc[nf][2] = __expf(sc[nf][2] - m1);
                sc[nf][3] = __expf(sc[nf][3] - m1);
                l0 += sc[nf][0] + sc[nf][1];
                l1 += sc[nf][2] + sc[nf][3];
            }

            // O += P V  (2-term: P fp16, V 22-bit)
            unsigned vh_b = kv_frag + (3 + buf) * HTB;
            unsigned vl_b = kv_frag + (6 + buf) * HTB;
            int nkb = nblkS >> 1;
            for (int kb = 0; kb < nkb; kb++) {
                unsigned ah[4];
                ah[0] = pack2(__float2half_rn(sc[2*kb][0]),   __float2half_rn(sc[2*kb][1]));
                ah[1] = pack2(__float2half_rn(sc[2*kb][2]),   __float2half_rn(sc[2*kb][3]));
                ah[2] = pack2(__float2half_rn(sc[2*kb+1][0]), __float2half_rn(sc[2*kb+1][1]));
                ah[3] = pack2(__float2half_rn(sc[2*kb+1][2]), __float2half_rn(sc[2*kb+1][3]));
#pragma unroll
                for (int p = 0; p < 4; p++) {
                    unsigned bh[4], bl[4];
                    ldsm_x4(bh, vh_b + p * 2304 + kb * 32);
                    ldsm_x4(bl, vl_b + p * 2304 + kb * 32);
                    mma_f16(oacc[2*p],   ah, bl,     oacc[2*p]);
                    mma_f16(oacc[2*p],   ah, bh,     oacc[2*p]);
                    mma_f16(oacc[2*p+1], ah, bl + 2, oacc[2*p+1]);
                    mma_f16(oacc[2*p+1], ah, bh + 2, oacc[2*p+1]);
                }
            }
        }
    }

    l0 += __shfl_xor_sync(0xffffffffu, l0, 1);
    l0 += __shfl_xor_sync(0xffffffffu, l0, 2);
    l1 += __shfl_xor_sync(0xffffffffu, l1, 1);
    l1 += __shfl_xor_sync(0xffffffffu, l1, 2);
    float inv0 = 1.0f / l0, inv1 = 1.0f / l1;

    size_t o0 = (size_t)(b * SEQ + qr0) * DMODEL + h * HDIM;
    size_t o1 = (size_t)(b * SEQ + qr1) * DMODEL + h * HDIM;
#pragma unroll
    for (int nf = 0; nf < 8; nf++) {
        int col = nf * 8 + 2 * c;
        *(unsigned*)&oh[o0 + col] = pack2(__float2half_rn(oacc[nf][0] * inv0),
                                          __float2half_rn(oacc[nf][1] * inv0));
        *(unsigned*)&oh[o1 + col] = pack2(__float2half_rn(oacc[nf][2] * inv1),
                                          __float2half_rn(oacc[nf][3] * inv1));
    }
}

// ---------------- launch ----------------
extern "C" void kernel_launch(void* const* d_in, const int* in_sizes, int n_in,
                              void* d_out, int out_size) {
    const float* x  = (const float*)d_in[0];
    const float* Wq = (const float*)d_in[1];
    const float* Wk = (const float*)d_in[2];
    const float* Wv = (const float*)d_in[3];
    const float* Wo = (const float*)d_in[4];
    float* out = (float*)d_out;

    cudaFuncSetAttribute(gemm_f16_kernel, cudaFuncAttributeMaxDynamicSharedMemorySize, GEMM_SMEM);
    cudaFuncSetAttribute(attn_f16_kernel, cudaFuncAttributeMaxDynamicSharedMemorySize, ATTN_SMEM);

    __half *xh, *xl, *wth, *wtl, *qh, *kh, *vth, *vtl, *ath;
    float *vraw, *ct, *st;
    cudaGetSymbolAddress((void**)&xh,   g_xh);
    cudaGetSymbolAddress((void**)&xl,   g_xl);
    cudaGetSymbolAddress((void**)&wth,  g_wth);
    cudaGetSymbolAddress((void**)&wtl,  g_wtl);
    cudaGetSymbolAddress((void**)&vraw, g_vraw);
    cudaGetSymbolAddress((void**)&qh,   g_qh);
    cudaGetSymbolAddress((void**)&kh,   g_kh);
    cudaGetSymbolAddress((void**)&vth,  g_vth);
    cudaGetSymbolAddress((void**)&vtl,  g_vtl);
    cudaGetSymbolAddress((void**)&ath,  g_ath);
    cudaGetSymbolAddress((void**)&ct,   g_cos);
    cudaGetSymbolAddress((void**)&st,   g_sin);

    {
        int n = SEQ * (HDIM/2);
        rope_table_kernel<<<(n + 255) / 256, 256>>>(ct, st);
    }

    split_x_kernel<<<(NELEM + 255) / 256, 256>>>(x, xh, xl, NELEM);
    wtrans_kernel<<<dim3(DMODEL/32, DMODEL/32, 4), dim3(32, 32)>>>(Wq, Wk, Wv, Wo, wth, wtl);

    // merged QKV projection with fused rope epilogue
    dim3 qkv_grid(DMODEL / 128, MROWS / 128, 3);
    gemm_f16_kernel<<<qkv_grid, 256, GEMM_SMEM>>>(xh, xl,
                                    wth + 0 * WELEM, wtl + 0 * WELEM,
                                    wth + 1 * WELEM, wtl + 1 * WELEM,
                                    wth + 2 * WELEM, wtl + 2 * WELEM,
                                    ct, st, qh, kh, vraw, nullptr, 0);

    vtrans_kernel<<<dim3(SEQ/32, DMODEL/32, BATCH), dim3(32, 32)>>>(vraw, vth, vtl);

    attn_f16_kernel<<<dim3(SEQ / 128, NHEADS, BATCH), 256, ATTN_SMEM>>>(
        qh, kh, vth, vtl, ath);

    // output projection (2-term)
    dim3 o_grid(DMODEL / 128, MROWS / 128, 1);
    gemm_f16_kernel<<<o_grid, 256, GEMM_SMEM>>>(ath, ath,
                                  wth + 3 * WELEM, wtl + 3 * WELEM,
                                  wth + 3 * WELEM, wtl + 3 * WELEM,
                                  wth + 3 * WELEM, wtl + 3 * WELEM,
                                  ct, st, nullptr, nullptr, nullptr, out, 1);
}

// round 17
// speedup vs baseline: 1.6919x; 1.2958x over previous
#include <cuda_runtime.h>
#include <cuda_fp16.h>
#include <cstdint>
#include <math.h>

#define BATCH 2
#define SEQ   2048
#define DMODEL 768
#define NHEADS 12
#define HDIM  64
#define MROWS (BATCH*SEQ)   // 4096
#define NELEM (MROWS*DMODEL)
#define WELEM (DMODEL*DMODEL)

// ---------------- scratch (device globals; allocation-free) ----------------
__device__ __half g_xh[NELEM];
__device__ __half g_wth[4][WELEM], g_wtl[4][WELEM];   // transposed [n][k], 22-bit
__device__ float  g_vraw[NELEM];
__device__ __half g_qh[NELEM];                         // Q fp16
__device__ __half g_kh[NELEM];                         // K fp16
__device__ __half g_vth[NELEM];                        // V^T fp16 [b][dglobal][t]
__device__ __half g_ath[NELEM];                        // attention out fp16
__device__ float  g_cos[SEQ * (HDIM/2)];
__device__ float  g_sin[SEQ * (HDIM/2)];

// ---------------- fp16 helpers ----------------
__device__ __forceinline__ void split_h(float x, __half& h, __half& l) {
    h = __float2half_rn(x);
    l = __float2half_rn(x - __half2float(h));
}
__device__ __forceinline__ unsigned pack2(__half a, __half b) {
    __half2 t = __halves2half2(a, b);
    return *(unsigned*)&t;
}
__device__ __forceinline__ void mma_f16(float* d, const unsigned* a, const unsigned* b, const float* c) {
    asm volatile(
        "mma.sync.aligned.m16n8k16.row.col.f32.f16.f16.f32 "
        "{%0,%1,%2,%3}, {%4,%5,%6,%7}, {%8,%9}, {%10,%11,%12,%13};\n"
        : "=f"(d[0]), "=f"(d[1]), "=f"(d[2]), "=f"(d[3])
        : "r"(a[0]), "r"(a[1]), "r"(a[2]), "r"(a[3]),
          "r"(b[0]), "r"(b[1]),
          "f"(c[0]), "f"(c[1]), "f"(c[2]), "f"(c[3]));
}
__device__ __forceinline__ void ldsm_x4(unsigned* r, unsigned addr) {
    asm volatile("ldmatrix.sync.aligned.m8n8.x4.shared.b16 {%0,%1,%2,%3}, [%4];"
        : "=r"(r[0]), "=r"(r[1]), "=r"(r[2]), "=r"(r[3]) : "r"(addr));
}

__device__ __forceinline__ void cp_async16(void* smem, const void* gmem) {
    unsigned s = (unsigned)__cvta_generic_to_shared(smem);
    asm volatile("cp.async.cg.shared.global [%0], [%1], 16;\n" :: "r"(s), "l"(gmem));
}
__device__ __forceinline__ void cp_commit() { asm volatile("cp.async.commit_group;\n"); }
template<int N> __device__ __forceinline__ void cp_wait() {
    asm volatile("cp.async.wait_group %0;\n" :: "n"(N));
}

// ---------------- prepass: x -> fp16 ----------------
__global__ void cvt_x_kernel(const float* __restrict__ src, __half* __restrict__ hi, int n) {
    int i = blockIdx.x * blockDim.x + threadIdx.x;
    if (i >= n) return;
    hi[i] = __float2half_rn(src[i]);
}

// ---------------- prepass: weight transpose + split -> Wt[n][k] (22-bit) ----------------
__global__ void wtrans_kernel(const float* __restrict__ w0, const float* __restrict__ w1,
                              const float* __restrict__ w2, const float* __restrict__ w3,
                              __half* __restrict__ hi, __half* __restrict__ lo) {
    __shared__ float t[32][33];
    int w = blockIdx.z;
    const float* W = (w == 0) ? w0 : (w == 1) ? w1 : (w == 2) ? w2 : w3;
    int k0 = blockIdx.x * 32, n0 = blockIdx.y * 32;
    int tx = threadIdx.x, ty = threadIdx.y;
    t[ty][tx] = W[(size_t)(k0 + ty) * DMODEL + n0 + tx];
    __syncthreads();
    float v = t[tx][ty];
    size_t o = (size_t)w * WELEM + (size_t)(n0 + ty) * DMODEL + k0 + tx;
    split_h(v, hi[o], lo[o]);
}

// ---------------- prepass: V transpose -> vt[b][dglobal][t] fp16 ----------------
__global__ void vtrans_kernel(const float* __restrict__ vraw, __half* __restrict__ hi) {
    __shared__ float t[32][33];
    int b = blockIdx.z;
    int t0 = blockIdx.x * 32, d0 = blockIdx.y * 32;
    int tx = threadIdx.x, ty = threadIdx.y;
    t[ty][tx] = vraw[(size_t)(b * SEQ + t0 + ty) * DMODEL + d0 + tx];
    __syncthreads();
    float v = t[tx][ty];
    size_t o = ((size_t)b * DMODEL + d0 + ty) * SEQ + t0 + tx;
    hi[o] = __float2half_rn(v);
}

// ---------------- RoPE table ----------------
__global__ void rope_table_kernel(float* ct, float* st) {
    int idx = blockIdx.x * blockDim.x + threadIdx.x;
    if (idx >= SEQ * (HDIM/2)) return;
    int t = idx >> 5;
    int i = idx & 31;
    float inv_freq = powf(10000.0f, -(float)(2 * i) / (float)HDIM);
    float ang = (float)t * inv_freq;
    ct[idx] = cosf(ang);
    st[idx] = sinf(ang);
}

// ---------------- 2-term FP16 GEMM: C = A_h @ (B_h + B_l)^T ----------------
// 128x128 tile, BK=32, 256 threads, warp 32x64.
// mode 0 (QKV): z=0 q -> rope+0.125, fp16; z=1 k -> rope, fp16; z=2 v -> f32.
// mode 1 (Wo):  plain f32 store.
#define GEMM_SMEM 61440   // halves: As_h[2][128][40]@0 | Bs_h@10240 | Bs_l@20480

__global__ __launch_bounds__(256, 2)
void gemm_f16_kernel(const __half* __restrict__ Ah,
                     const __half* __restrict__ B0h, const __half* __restrict__ B0l,
                     const __half* __restrict__ B1h, const __half* __restrict__ B1l,
                     const __half* __restrict__ B2h, const __half* __restrict__ B2l,
                     const float* __restrict__ ct, const float* __restrict__ st,
                     __half* __restrict__ qh, __half* __restrict__ kh,
                     float* __restrict__ vout, float* __restrict__ Cplain, int mode) {
    const int K = DMODEL;
    extern __shared__ __half smh[];

    int z = blockIdx.z;
    const __half* Bh = (z == 0) ? B0h : (z == 1) ? B1h : B2h;
    const __half* Bl = (z == 0) ? B0l : (z == 1) ? B1l : B2l;

    int tid  = threadIdx.x;
    int wid  = tid >> 5, lane = tid & 31;
    int g = lane >> 2, c = lane & 3;
    int wm = (wid & 3) * 32;
    int wn = (wid >> 2) * 64;
    int bm = blockIdx.y * 128, bn = blockIdx.x * 128;

    int lrow = tid >> 1, lseg = (tid & 1) * 16;

    unsigned smem_u = (unsigned)__cvta_generic_to_shared(smh);
    unsigned a_frag = smem_u + ((wm + (lane & 15)) * 40 + ((lane & 16) ? 8 : 0)) * 2;
    unsigned b_frag = smem_u + 20480 +
                      ((wn + (lane & 7) + ((lane & 16) ? 8 : 0)) * 40 + ((lane & 8) ? 8 : 0)) * 2;

    float acc[2][8][4];
#pragma unroll
    for (int mf = 0; mf < 2; mf++)
#pragma unroll
        for (int nf = 0; nf < 8; nf++)
#pragma unroll
            for (int j = 0; j < 4; j++) acc[mf][nf][j] = 0.0f;

    auto load_chunk = [&](int buf, int k0) {
        size_t ga = (size_t)(bm + lrow) * K + k0 + lseg;
        __half* da_h = smh + buf * 5120 + lrow * 40 + lseg;
        cp_async16(da_h,     Ah + ga);
        cp_async16(da_h + 8, Ah + ga + 8);
        size_t gb = (size_t)(bn + lrow) * K + k0 + lseg;
        __half* db_h = smh + 10240 + buf * 5120 + lrow * 40 + lseg;
        __half* db_l = db_h + 10240;
        cp_async16(db_h,     Bh + gb);
        cp_async16(db_h + 8, Bh + gb + 8);
        cp_async16(db_l,     Bl + gb);
        cp_async16(db_l + 8, Bl + gb + 8);
    };

    const int NCH = K / 32;  // 24
    load_chunk(0, 0); cp_commit();

    for (int ch = 0; ch < NCH; ch++) {
        int buf = ch & 1;
        if (ch + 1 < NCH) { load_chunk(buf ^ 1, (ch + 1) * 32); cp_commit(); cp_wait<1>(); }
        else              { cp_wait<0>(); }
        __syncthreads();

        unsigned abase = a_frag + buf * 10240;
        unsigned bbase = b_frag + buf * 10240;
#pragma unroll
        for (int ks = 0; ks < 2; ks++) {
            int kb = ks * 32;
            unsigned afh[2][4], bfh[8][2], bfl[8][2];
            ldsm_x4(afh[0], abase + kb);
            ldsm_x4(afh[1], abase + 1280 + kb);
#pragma unroll
            for (int p = 0; p < 4; p++) {
                unsigned r[4];
                ldsm_x4(r, bbase + p * 1280 + kb);
                bfh[2*p][0] = r[0]; bfh[2*p][1] = r[1]; bfh[2*p+1][0] = r[2]; bfh[2*p+1][1] = r[3];
                ldsm_x4(r, bbase + 20480 + p * 1280 + kb);
                bfl[2*p][0] = r[0]; bfl[2*p][1] = r[1]; bfl[2*p+1][0] = r[2]; bfl[2*p+1][1] = r[3];
            }
#pragma unroll
            for (int mf = 0; mf < 2; mf++)
#pragma unroll
                for (int nf = 0; nf < 8; nf++) {
                    mma_f16(acc[mf][nf], afh[mf], bfl[nf], acc[mf][nf]);
                    mma_f16(acc[mf][nf], afh[mf], bfh[nf], acc[mf][nf]);
                }
        }
        __syncthreads();
    }

    // ---------------- epilogue ----------------
    if (mode == 1) {
#pragma unroll
        for (int mf = 0; mf < 2; mf++) {
            int row0 = bm + wm + mf * 16 + g;
#pragma unroll
            for (int nf = 0; nf < 8; nf++) {
                int col = bn + wn + nf * 8 + 2 * c;
                *(float2*)(Cplain + (size_t)row0 * DMODEL + col)       = make_float2(acc[mf][nf][0], acc[mf][nf][1]);
                *(float2*)(Cplain + (size_t)(row0 + 8) * DMODEL + col) = make_float2(acc[mf][nf][2], acc[mf][nf][3]);
            }
        }
        return;
    }
    if (z == 2) {
#pragma unroll
        for (int mf = 0; mf < 2; mf++) {
            int row0 = bm + wm + mf * 16 + g;
#pragma unroll
            for (int nf = 0; nf < 8; nf++) {
                int col = bn + wn + nf * 8 + 2 * c;
                *(float2*)(vout + (size_t)row0 * DMODEL + col)       = make_float2(acc[mf][nf][0], acc[mf][nf][1]);
                *(float2*)(vout + (size_t)(row0 + 8) * DMODEL + col) = make_float2(acc[mf][nf][2], acc[mf][nf][3]);
            }
        }
        return;
    }
    // z==0 (q, scale 0.125) or z==1 (k): rope, store fp16
    {
        bool isq = (z == 0);
        __half* oh_ = isq ? qh : kh;
        float scale = isq ? 0.125f : 1.0f;
#pragma unroll
        for (int mf = 0; mf < 2; mf++) {
#pragma unroll
            for (int rs = 0; rs < 2; rs++) {
                int row = bm + wm + mf * 16 + g + rs * 8;
                int t = row & (SEQ - 1);
#pragma unroll
                for (int nf = 0; nf < 4; nf++) {
                    int i0 = nf * 8 + 2 * c;
                    float a0 = acc[mf][nf][rs * 2 + 0];
                    float a1 = acc[mf][nf][rs * 2 + 1];
                    float b0 = acc[mf][nf + 4][rs * 2 + 0];
                    float b1 = acc[mf][nf + 4][rs * 2 + 1];
                    float c0 = ct[t * 32 + i0],     s0 = st[t * 32 + i0];
                    float c1 = ct[t * 32 + i0 + 1], s1 = st[t * 32 + i0 + 1];
                    float rA0 = (a0 * c0 - b0 * s0) * scale;
                    float rB0 = (a0 * s0 + b0 * c0) * scale;
                    float rA1 = (a1 * c1 - b1 * s1) * scale;
                    float rB1 = (a1 * s1 + b1 * c1) * scale;
                    size_t o = (size_t)row * DMODEL + bn + wn + i0;
                    *(unsigned*)&oh_[o]      = pack2(__float2half_rn(rA0), __float2half_rn(rA1));
                    *(unsigned*)&oh_[o + 32] = pack2(__float2half_rn(rB0), __float2half_rn(rB1));
                }
            }
        }
    }
}

// ---------------- causal flash attention: 1-term S, 1-term PV ----------------
#define HTSZ (64 * 72)                 // halves per tile (144B rows, 16B-aligned)
#define HTB  (HTSZ * 2)                // 9216 B
#define ATTN_SMEM (6 * HTB)            // 55296 B : KH[3] | VH[3]

__global__ __launch_bounds__(256, 2)
void attn_f16_kernel(const __half* __restrict__ qh,
                     const __half* __restrict__ kh,
                     const __half* __restrict__ vth,
                     __half* __restrict__ oh) {
    extern __shared__ __half sm[];

    int qt = gridDim.x - 1 - blockIdx.x;   // heaviest blocks first
    int h = blockIdx.y, b = blockIdx.z;
    int tid = threadIdx.x;
    int warp = tid >> 5, lane = tid & 31;
    int g = lane >> 2, c = lane & 3;
    int qbase_w = qt * 128 + warp * 16;

    unsigned smem_u = (unsigned)__cvta_generic_to_shared(sm);
    unsigned kv_frag = smem_u + ((lane & 7) + ((lane & 16) ? 8 : 0)) * 144 + ((lane & 8) ? 16 : 0);

    unsigned qfh[4][4];
    {
        size_t b0 = (size_t)(b * SEQ + qbase_w + g)     * DMODEL + h * HDIM;
        size_t b1 = (size_t)(b * SEQ + qbase_w + g + 8) * DMODEL + h * HDIM;
#pragma unroll
        for (int ks = 0; ks < 4; ks++) {
            int k0 = ks * 16 + 2 * c;
            qfh[ks][0] = *(const unsigned*)&qh[b0 + k0];
            qfh[ks][1] = *(const unsigned*)&qh[b1 + k0];
            qfh[ks][2] = *(const unsigned*)&qh[b0 + k0 + 8];
            qfh[ks][3] = *(const unsigned*)&qh[b1 + k0 + 8];
        }
    }

    float oacc[8][4];
#pragma unroll
    for (int nf = 0; nf < 8; nf++)
#pragma unroll
        for (int j = 0; j < 4; j++) oacc[nf][j] = 0.0f;
    float m0 = -1e30f, m1 = -1e30f, l0 = 0.0f, l1 = 0.0f;
    int qr0 = qbase_w + g;
    int qr1 = qr0 + 8;

    auto load_kv = [&](int buf, int kt) {
        size_t kb_ = (size_t)(b * SEQ + kt * 64) * DMODEL + h * HDIM;
        size_t vb_ = ((size_t)b * DMODEL + h * HDIM) * SEQ + kt * 64;
        __half* dkh = sm + buf * HTSZ;
        __half* dvh = sm + (3 + buf) * HTSZ;
#pragma unroll
        for (int i = tid; i < 64 * 8; i += 256) {
            int row = i >> 3, seg = (i & 7) * 8;
            int so = row * 72 + seg;
            cp_async16(dkh + so, kh  + kb_ + (size_t)row * DMODEL + seg);
            cp_async16(dvh + so, vth + vb_ + (size_t)row * SEQ    + seg);
        }
    };

    const int kt_max = 2 * qt + 1;
    load_kv(0, 0); cp_commit();
    if (kt_max >= 1) { load_kv(1, 1); cp_commit(); }

    for (int kt = 0; kt <= kt_max; kt++) {
        int buf = kt % 3;
        if (kt < kt_max) cp_wait<1>(); else cp_wait<0>();
        __syncthreads();
        if (kt + 2 <= kt_max) { load_kv((kt + 2) % 3, kt + 2); cp_commit(); }

        int rel = qbase_w + 15 - kt * 64;
        int nblk = (rel < 0) ? 0 : min(8, (rel >> 3) + 1);
        int nblkS = (nblk + 1) & ~1;
        bool need_mask = (kt * 64 + 63 > qbase_w);

        if (nblkS > 0) {
            unsigned kh_b = kv_frag + buf * HTB;

            // S = Q K^T  (1-term)
            float sc[8][4];
            int npair = nblkS >> 1;
            for (int p = 0; p < npair; p++) {
#pragma unroll
                for (int j = 0; j < 4; j++) { sc[2*p][j] = 0.0f; sc[2*p+1][j] = 0.0f; }
#pragma unroll
                for (int ks = 0; ks < 4; ks++) {
                    unsigned bh[4];
                    ldsm_x4(bh, kh_b + p * 2304 + ks * 32);
                    mma_f16(sc[2*p],   qfh[ks], bh,     sc[2*p]);
                    mma_f16(sc[2*p+1], qfh[ks], bh + 2, sc[2*p+1]);
                }
            }

            if (need_mask) {
                for (int nf = 0; nf < nblkS; nf++) {
#pragma unroll
                    for (int j = 0; j < 4; j++) {
                        int key = kt * 64 + nf * 8 + 2 * c + (j & 1);
                        int qr  = (j < 2) ? qr0 : qr1;
                        if (key > qr) sc[nf][j] = -1e30f;
                    }
                }
            }

            float mx0 = -1e30f, mx1 = -1e30f;
            for (int nf = 0; nf < nblkS; nf++) {
                mx0 = fmaxf(mx0, fmaxf(sc[nf][0], sc[nf][1]));
                mx1 = fmaxf(mx1, fmaxf(sc[nf][2], sc[nf][3]));
            }
            mx0 = fmaxf(mx0, __shfl_xor_sync(0xffffffffu, mx0, 1));
            mx0 = fmaxf(mx0, __shfl_xor_sync(0xffffffffu, mx0, 2));
            mx1 = fmaxf(mx1, __shfl_xor_sync(0xffffffffu, mx1, 1));
            mx1 = fmaxf(mx1, __shfl_xor_sync(0xffffffffu, mx1, 2));
            float nm0 = fmaxf(m0, mx0), nm1 = fmaxf(m1, mx1);
            float cor0 = __expf(m0 - nm0), cor1 = __expf(m1 - nm1);
            m0 = nm0; m1 = nm1;
            l0 *= cor0; l1 *= cor1;
#pragma unroll
            for (int nf = 0; nf < 8; nf++) {
                oacc[nf][0] *= cor0; oacc[nf][1] *= cor0;
                oacc[nf][2] *= cor1; oacc[nf][3] *= cor1;
            }
            for (int nf = 0; nf < nblkS; nf++) {
                sc[nf][0] = __expf(sc[nf][0] - m0);
                sc[nf][1] = __expf(sc[nf][1] - m0);
                sc[nf][2] = __expf(sc[nf][2] - m1);
                sc[nf][3] = __expf(sc[nf][3] - m1);
                l0 += sc[nf][0] + sc[nf][1];
                l1 += sc[nf][2] + sc[nf][3];
            }

            // O += P V  (1-term)
            unsigned vh_b = kv_frag + (3 + buf) * HTB;
            int nkb = nblkS >> 1;
            for (int kb = 0; kb < nkb; kb++) {
                unsigned ah[4];
                ah[0] = pack2(__float2half_rn(sc[2*kb][0]),   __float2half_rn(sc[2*kb][1]));
                ah[1] = pack2(__float2half_rn(sc[2*kb][2]),   __float2half_rn(sc[2*kb][3]));
                ah[2] = pack2(__float2half_rn(sc[2*kb+1][0]), __float2half_rn(sc[2*kb+1][1]));
                ah[3] = pack2(__float2half_rn(sc[2*kb+1][2]), __float2half_rn(sc[2*kb+1][3]));
#pragma unroll
                for (int p = 0; p < 4; p++) {
                    unsigned bh[4];
                    ldsm_x4(bh, vh_b + p * 2304 + kb * 32);
                    mma_f16(oacc[2*p],   ah, bh,     oacc[2*p]);
                    mma_f16(oacc[2*p+1], ah, bh + 2, oacc[2*p+1]);
                }
            }
        }
    }

    l0 += __shfl_xor_sync(0xffffffffu, l0, 1);
    l0 += __shfl_xor_sync(0xffffffffu, l0, 2);
    l1 += __shfl_xor_sync(0xffffffffu, l1, 1);
    l1 += __shfl_xor_sync(0xffffffffu, l1, 2);
    float inv0 = 1.0f / l0, inv1 = 1.0f / l1;

    size_t o0 = (size_t)(b * SEQ + qr0) * DMODEL + h * HDIM;
    size_t o1 = (size_t)(b * SEQ + qr1) * DMODEL + h * HDIM;
#pragma unroll
    for (int nf = 0; nf < 8; nf++) {
        int col = nf * 8 + 2 * c;
        *(unsigned*)&oh[o0 + col] = pack2(__float2half_rn(oacc[nf][0] * inv0),
                                          __float2half_rn(oacc[nf][1] * inv0));
        *(unsigned*)&oh[o1 + col] = pack2(__float2half_rn(oacc[nf][2] * inv1),
                                          __float2half_rn(oacc[nf][3] * inv1));
    }
}

// ---------------- launch ----------------
extern "C" void kernel_launch(void* const* d_in, const int* in_sizes, int n_in,
                              void* d_out, int out_size) {
    const float* x  = (const float*)d_in[0];
    const float* Wq = (const float*)d_in[1];
    const float* Wk = (const float*)d_in[2];
    const float* Wv = (const float*)d_in[3];
    const float* Wo = (const float*)d_in[4];
    float* out = (float*)d_out;

    cudaFuncSetAttribute(gemm_f16_kernel, cudaFuncAttributeMaxDynamicSharedMemorySize, GEMM_SMEM);
    cudaFuncSetAttribute(attn_f16_kernel, cudaFuncAttributeMaxDynamicSharedMemorySize, ATTN_SMEM);

    __half *xh, *wth, *wtl, *qh, *kh, *vth, *ath;
    float *vraw, *ct, *st;
    cudaGetSymbolAddress((void**)&xh,   g_xh);
    cudaGetSymbolAddress((void**)&wth,  g_wth);
    cudaGetSymbolAddress((void**)&wtl,  g_wtl);
    cudaGetSymbolAddress((void**)&vraw, g_vraw);
    cudaGetSymbolAddress((void**)&qh,   g_qh);
    cudaGetSymbolAddress((void**)&kh,   g_kh);
    cudaGetSymbolAddress((void**)&vth,  g_vth);
    cudaGetSymbolAddress((void**)&ath,  g_ath);
    cudaGetSymbolAddress((void**)&ct,   g_cos);
    cudaGetSymbolAddress((void**)&st,   g_sin);

    {
        int n = SEQ * (HDIM/2);
        rope_table_kernel<<<(n + 255) / 256, 256>>>(ct, st);
    }

    cvt_x_kernel<<<(NELEM + 255) / 256, 256>>>(x, xh, NELEM);
    wtrans_kernel<<<dim3(DMODEL/32, DMODEL/32, 4), dim3(32, 32)>>>(Wq, Wk, Wv, Wo, wth, wtl);

    // merged QKV projection with fused rope epilogue (all 2-term)
    dim3 qkv_grid(DMODEL / 128, MROWS / 128, 3);
    gemm_f16_kernel<<<qkv_grid, 256, GEMM_SMEM>>>(xh,
                                    wth + 0 * WELEM, wtl + 0 * WELEM,
                                    wth + 1 * WELEM, wtl + 1 * WELEM,
                                    wth + 2 * WELEM, wtl + 2 * WELEM,
                                    ct, st, qh, kh, vraw, nullptr, 0);

    vtrans_kernel<<<dim3(SEQ/32, DMODEL/32, BATCH), dim3(32, 32)>>>(vraw, vth);

    attn_f16_kernel<<<dim3(SEQ / 128, NHEADS, BATCH), 256, ATTN_SMEM>>>(
        qh, kh, vth, ath);

    // output projection (2-term)
    dim3 o_grid(DMODEL / 128, MROWS / 128, 1);
    gemm_f16_kernel<<<o_grid, 256, GEMM_SMEM>>>(ath,
                                  wth + 3 * WELEM, wtl + 3 * WELEM,
                                  wth + 3 * WELEM, wtl + 3 * WELEM,
                                  wth + 3 * WELEM, wtl + 3 * WELEM,
                                  ct, st, nullptr, nullptr, nullptr, out, 1);
}